// round 14
// baseline (speedup 1.0000x reference)
#include <cuda_runtime.h>
#include <cuda_bf16.h>
#include <cuda_fp16.h>
#include <math.h>
#include <cstdint>

#define Bz 64
#define Nn 196
#define Tt 32
#define Ss 31
#define VD 128
#define EM 256
#define AT 256
#define HD 512
#define VOC 30000
#define VOCP 30080
#define KX 384      // EM + VD
#define KG 896      // EM + VD + HD
#define JG 2048     // 4*HD
#define RTOT 1984   // Ss*Bz
#define RP 2048
#define K2 768      // logit split-concat K
#define KG2 2688    // lstm split-concat K = 3*896
#define NSPL 7      // lstm K-splits
#define NSPLA 3     // attn n-splits (66/66/64)

typedef unsigned long long ULL;

// ---------------- scratch (device globals; zero-initialized, no allocation) ----------------
__device__ float g_h[2][Bz*HD];
__device__ float g_c[2][Bz*HD];
__device__ float g_H[Ss*Bz*HD];
__device__ float g_WwT[HD*AT];                 // Ww transposed [k][a]
__device__ float g_gb[JG];                     // bih + bhh
__device__ float g_part[16*NSPL*64*128];       // lstm partial gates
__device__ int   g_cnt[16];                    // lstm arrival counters (reset in-kernel)
__device__ float g_attp[Bz*NSPLA*132];         // attn partials: {ctx[128], m, s}
__device__ int   g_acnt[Bz];                   // attn ctx arrival counters (reset in-kernel)
__device__ float g_whp[Bz*NSPLA*AT];           // Wh k-slice partials
__device__ int   g_wcnt[Bz];                   // Wh spin counters (monotonic per replay; reset in prep)
__device__ __half g_UVh[Bz*Nn*AT];             // UV in fp16 (6.4MB)
__device__ __half g_Vh[Bz*Nn*VD];              // V copy in fp16 (3.2MB)
__device__ __nv_bfloat16 g_Axc[Bz*KG2];        // per-step xc rows [hi|hi|lo]
__device__ __nv_bfloat16 g_Wg2[JG*KG2];        // gate-interleaved weight rows [hi|lo|hi]
__device__ __nv_bfloat16 g_A2[RP*K2];          // E split-concat rows [hi|hi|lo]; pad rows stay 0
__device__ __nv_bfloat16 g_B2[VOCP*K2];        // embed split-concat rows [hi|lo|hi]; pad rows stay 0

// ---------------- helpers ----------------
__device__ __forceinline__ float sigf(float x){ return __fdividef(1.0f, 1.0f + __expf(-x)); }
__device__ __forceinline__ float tanhacc(float x){
    return __fdividef(2.0f, 1.0f + __expf(-2.0f*x)) - 1.0f;
}
__device__ __forceinline__ __half2 htanh2(__half2 x){
    uint32_t r, xi = *(uint32_t*)&x;
    asm("tanh.approx.f16x2 %0, %1;" : "=r"(r) : "r"(xi));
    return *(__half2*)&r;
}
__device__ __forceinline__ uint32_t smem_to_u32(const void* smem_ptr){
    uint32_t addr;
    asm("{ .reg .u64 tmp; cvta.to.shared.u64 tmp, %1; cvt.u32.u64 %0, tmp; }"
        : "=r"(addr) : "l"(smem_ptr));
    return addr;
}
#define SWZ(o) ((o) ^ (((o) >> 3) & 0x70))

__device__ __forceinline__ void ldmatrix_x4(uint32_t& r0, uint32_t& r1, uint32_t& r2, uint32_t& r3,
                                            uint32_t addr){
    asm volatile("ldmatrix.sync.aligned.m8n8.x4.shared.b16 {%0,%1,%2,%3}, [%4];"
                 : "=r"(r0), "=r"(r1), "=r"(r2), "=r"(r3) : "r"(addr));
}
__device__ __forceinline__ void mma16816(float* d, const uint32_t* a, uint32_t b0, uint32_t b1){
    asm volatile("mma.sync.aligned.m16n8k16.row.col.f32.bf16.bf16.f32 "
                 "{%0,%1,%2,%3}, {%4,%5,%6,%7}, {%8,%9}, {%0,%1,%2,%3};"
                 : "+f"(d[0]), "+f"(d[1]), "+f"(d[2]), "+f"(d[3])
                 : "r"(a[0]), "r"(a[1]), "r"(a[2]), "r"(a[3]), "r"(b0), "r"(b1));
}
__device__ __forceinline__ void cp_async16(uint32_t dst, const void* src){
    asm volatile("cp.async.cg.shared.global [%0], [%1], 16;" :: "r"(dst), "l"(src) : "memory");
}
__device__ __forceinline__ void split_bf16(float x, __nv_bfloat16& h, __nv_bfloat16& l){
    h = __float2bfloat16(x);
    l = __float2bfloat16(x - __bfloat162float(h));
}

// ---------------- embed -> split-concat bf16 rows: B = [hi|lo|hi] ----------------
__global__ void __launch_bounds__(256) conv_embed_kernel(const float* __restrict__ embed){
    size_t i = ((size_t)blockIdx.x*256 + threadIdx.x)*4;
    size_t v = i / EM;
    int k = (int)(i % EM);
    float4 x = *(const float4*)(embed + i);
    float xs[4] = {x.x, x.y, x.z, x.w};
    unsigned short h[4], l[4];
    #pragma unroll
    for (int j = 0; j < 4; j++){
        __nv_bfloat16 hb, lb; split_bf16(xs[j], hb, lb);
        h[j] = __bfloat16_as_ushort(hb);
        l[j] = __bfloat16_as_ushort(lb);
    }
    uint2 hv, lv;
    hv.x = (uint32_t)h[0] | ((uint32_t)h[1] << 16);
    hv.y = (uint32_t)h[2] | ((uint32_t)h[3] << 16);
    lv.x = (uint32_t)l[0] | ((uint32_t)l[1] << 16);
    lv.y = (uint32_t)l[2] | ((uint32_t)l[3] << 16);
    __nv_bfloat16* row = g_B2 + v*K2;
    *(uint2*)(row + k)       = hv;
    *(uint2*)(row + 256 + k) = lv;
    *(uint2*)(row + 512 + k) = hv;
}

// ---------------- one-shot prep: Wg2 rows + misc + WwT transpose ----------------
__global__ void __launch_bounds__(256) prep_w_kernel(const float* __restrict__ Wih,
                                                     const float* __restrict__ Whh,
                                                     const float* __restrict__ Ww,
                                                     const float* __restrict__ bih,
                                                     const float* __restrict__ bhh){
    int bx = blockIdx.x, tid = threadIdx.x;
    if (bx < JG){
        int tile = bx >> 7;
        int within = bx & 127;
        int gate = within >> 5;
        int uu = within & 31;
        int j = gate*HD + tile*32 + uu;
        __nv_bfloat16* row = g_Wg2 + (size_t)bx*KG2;
        for (int k = tid; k < KG; k += 256){
            float w = (k < KX) ? Wih[(size_t)j*KX + k] : Whh[(size_t)j*HD + (k - KX)];
            __nv_bfloat16 hb, lb; split_bf16(w, hb, lb);
            row[k]        = hb;
            row[KG + k]   = lb;
            row[2*KG + k] = hb;
        }
    } else if (bx < JG + 8){
        int bb = bx - JG;
        int idx = bb*256 + tid;           // 0..2047
        g_gb[idx] = bih[idx] + bhh[idx];
        if (idx < Bz) g_wcnt[idx] = 0;    // reset Wh spin counters each replay
        #pragma unroll
        for (int i = 0; i < 16; i++){
            int z = idx*16 + i;
            g_h[0][z] = 0.f;
            g_c[0][z] = 0.f;
        }
    } else {
        __shared__ float t[32][33];
        int bx2 = bx - (JG + 8);
        int a0 = (bx2 & 7)*32;
        int k0 = (bx2 >> 3)*32;
        int tx = tid & 31, ty = tid >> 5;
        #pragma unroll
        for (int i = 0; i < 4; i++)
            t[ty + i*8][tx] = Ww[(size_t)(a0 + ty + i*8)*HD + k0 + tx];
        __syncthreads();
        #pragma unroll
        for (int i = 0; i < 4; i++)
            g_WwT[(size_t)(k0 + ty + i*8)*AT + a0 + tx] = t[tx][ty + i*8];
    }
}

// ---------------- UV (writes fp16 UV + fp16 V copy) ----------------
__global__ void __launch_bounds__(256) uv_kernel(const float* __restrict__ V,
                                                 const float* __restrict__ Uw,
                                                 const float* __restrict__ Ub){
    int b = blockIdx.x;
    int n0 = blockIdx.y * 32;
    int tid = threadIdx.x;
    __shared__ __align__(16) float sV[32][VD];
    for (int e = tid; e < 32*VD; e += 256){
        int n = n0 + (e / VD);
        float v = (n < Nn) ? V[((size_t)b*Nn + n)*VD + (e % VD)] : 0.f;
        sV[e / VD][e % VD] = v;
        if (n < Nn) g_Vh[((size_t)b*Nn + n)*VD + (e % VD)] = __float2half_rn(v);
    }
    __syncthreads();
    int a = tid;
    float acc[32];
    #pragma unroll
    for (int n = 0; n < 32; n++) acc[n] = 0.f;
    for (int kc = 0; kc < VD; kc += 16){
        float u[16];
        #pragma unroll
        for (int i = 0; i < 16; i += 4)
            *(float4*)&u[i] = *(const float4*)&Uw[a*VD + kc + i];
        #pragma unroll
        for (int n = 0; n < 32; n++){
            #pragma unroll
            for (int k = 0; k < 16; k++)
                acc[n] += u[k] * sV[n][kc + k];
        }
    }
    float ub = Ub[a];
    #pragma unroll
    for (int n = 0; n < 32; n++){
        int nn = n0 + n;
        if (nn < Nn) g_UVh[((size_t)b*Nn + nn)*AT + a] = __float2half_rn(acc[n] + ub);
    }
}

// ---------------- fused Wh + attention (flash n-split, f16x2 tanh). grid (64,3), 1024 thr ----------------
__global__ void __launch_bounds__(1024) attn_kernel(const int* __restrict__ y,
                                                    const float* __restrict__ embed,
                                                    const float* __restrict__ Wb,
                                                    const float* __restrict__ vw,
                                                    const float* __restrict__ vb,
                                                    int step, int p){
    __shared__ __align__(16) float sh[HD];
    __shared__ __align__(16) float sP[1024];
    __shared__ __align__(16) __half2 sWh2[AT/2];
    __shared__ __align__(16) float sv[AT];
    __shared__ __align__(16) float se[68];
    __shared__ __align__(16) float sred[32];
    __shared__ __align__(16) float s_sc[4];
    __shared__ __align__(16) float sctx[VD];
    __shared__ __align__(16) float4 sc4[32][32];
    __shared__ int s_old;

    int b = blockIdx.x, sp = blockIdx.y, tid = threadIdx.x;
    int warp = tid >> 5, lane = tid & 31;
    int n0 = sp*66;
    int n1 = (sp == NSPLA-1) ? Nn : n0 + 66;
    int cnt = n1 - n0;

    if (tid < HD) sh[tid] = g_h[p][b*HD + tid];
    if (tid < AT) sv[tid] = vw[tid];
    __syncthreads();

    // ---- phase 0: Wh k-slice partial. k-range [sp*171, ...], all 256 a
    {
        int k0 = sp*171;
        int k1 = (sp == NSPLA-1) ? HD : k0 + 171;
        int a = tid & 255, kq = tid >> 8;
        float acc = 0.f;
        for (int k = k0 + kq; k < k1; k += 4)
            acc += sh[k] * g_WwT[(size_t)k*AT + a];
        sP[tid] = acc;
    }
    __syncthreads();
    if (tid < AT)
        g_whp[(size_t)(b*NSPLA + sp)*AT + tid] =
            sP[tid] + sP[256 + tid] + sP[512 + tid] + sP[768 + tid];
    __threadfence();
    __syncthreads();
    if (tid == 0){
        atomicAdd(&g_wcnt[b], 1);
        int target = NSPLA*(step + 1);     // monotonic within one replay
        while (atomicAdd(&g_wcnt[b], 0) < target){ __nanosleep(64); }
    }
    __syncthreads();
    __threadfence();
    if (tid < AT/2){
        const float* W0 = g_whp + (size_t)b*NSPLA*AT;
        int a0 = 2*tid, a1 = 2*tid + 1;
        float x0 = W0[a0] + W0[AT + a0] + W0[2*AT + a0] + Wb[a0];
        float x1 = W0[a1] + W0[AT + a1] + W0[2*AT + a1] + Wb[a1];
        sWh2[tid] = __floats2half2_rn(x0, x1);
    }
    __syncthreads();

    // ---- local e_n = v . tanh(Wh + UV[n]) + vb   (f16x2 tanh: 1 MUFU per pair)
    float vbias = vb[0];
    for (int n = n0 + warp; n < n1; n += 32){
        const uint32_t* uvp = (const uint32_t*)(g_UVh + ((size_t)b*Nn + n)*AT);
        float pz = 0.f;
        #pragma unroll
        for (int j = 0; j < 4; j++){
            int idx = lane + j*32;
            uint32_t pa = uvp[idx];
            __half2 s2 = __hadd2(sWh2[idx], *(__half2*)&pa);
            float2 t = __half22float2(htanh2(s2));
            float2 v2 = *(const float2*)&sv[2*idx];
            pz += t.x*v2.x + t.y*v2.y;
        }
        #pragma unroll
        for (int o = 16; o; o >>= 1) pz += __shfl_xor_sync(0xffffffffu, pz, o);
        if (lane == 0) se[n - n0] = pz + vbias;
    }
    __syncthreads();

    // ---- local max + exp + sum
    float m = (tid < cnt) ? se[tid] : -1e30f;
    #pragma unroll
    for (int o = 16; o; o >>= 1) m = fmaxf(m, __shfl_xor_sync(0xffffffffu, m, o));
    if (lane == 0) sred[warp] = m;
    __syncthreads();
    if (tid == 0){
        float mm = sred[0];
        #pragma unroll
        for (int i = 1; i < 3; i++) mm = fmaxf(mm, sred[i]);
        s_sc[0] = mm;
    }
    __syncthreads();
    float mloc = s_sc[0];
    float ex = (tid < cnt) ? __expf(se[tid] - mloc) : 0.f;
    if (tid < cnt) se[tid] = ex;
    float sum = ex;
    #pragma unroll
    for (int o = 16; o; o >>= 1) sum += __shfl_xor_sync(0xffffffffu, sum, o);
    if (lane == 0) sred[warp] = sum;
    __syncthreads();
    if (tid == 0){
        s_sc[1] = sred[0] + sred[1] + sred[2];
    }
    __syncthreads();

    // ---- partial ctx
    float4 a4 = {0.f, 0.f, 0.f, 0.f};
    for (int n = n0 + warp; n < n1; n += 32){
        float w = se[n - n0];
        uint2 pv = *(const uint2*)(g_Vh + ((size_t)b*Nn + n)*VD + lane*4);
        float2 lo = __half22float2(*(__half2*)&pv.x);
        float2 hi = __half22float2(*(__half2*)&pv.y);
        a4.x += w*lo.x; a4.y += w*lo.y; a4.z += w*hi.x; a4.w += w*hi.y;
    }
    sc4[warp][lane] = a4;
    __syncthreads();
    #pragma unroll
    for (int off = 16; off; off >>= 1){
        if (warp < off){
            float4 x = sc4[warp][lane], y4 = sc4[warp + off][lane];
            x.x += y4.x; x.y += y4.y; x.z += y4.z; x.w += y4.w;
            sc4[warp][lane] = x;
        }
        __syncthreads();
    }

    // ---- write partial {ctx[128], m, s}
    float* P = g_attp + (size_t)(b*NSPLA + sp)*132;
    if (tid < 32){
        float4 cv = sc4[0][tid];
        *(float4*)&P[tid*4] = cv;
    }
    if (tid == 32) P[128] = mloc;
    if (tid == 33) P[129] = s_sc[1];
    __threadfence();
    __syncthreads();
    if (tid == 0) s_old = atomicAdd(&g_acnt[b], 1);
    __syncthreads();
    if (s_old != NSPLA - 1) return;

    // ---- last arriver: combine partials + xc epilogue
    __threadfence();
    const float* P0 = g_attp + (size_t)b*NSPLA*132;
    if (tid == 0){
        float m0 = P0[128], m1 = P0[132 + 128], m2 = P0[264 + 128];
        float mg = fmaxf(m0, fmaxf(m1, m2));
        float w0 = __expf(m0 - mg), w1 = __expf(m1 - mg), w2 = __expf(m2 - mg);
        float tot = P0[129]*w0 + P0[132 + 129]*w1 + P0[264 + 129]*w2;
        s_sc[0] = w0; s_sc[1] = w1; s_sc[2] = w2; s_sc[3] = 1.0f / tot;
        g_acnt[b] = 0;
    }
    __syncthreads();
    if (tid < VD){
        float w0 = s_sc[0], w1 = s_sc[1], w2 = s_sc[2], inv = s_sc[3];
        float cv = P0[tid]*w0 + P0[132 + tid]*w1 + P0[264 + tid]*w2;
        sctx[tid] = cv * inv;
    }
    __syncthreads();

    if (tid < KG){
        int tok = y[b*Tt + step];
        float v;
        if (tid < EM)      v = embed[(size_t)tok*EM + tid];
        else if (tid < KX) v = sctx[tid - EM];
        else               v = sh[tid - KX];
        __nv_bfloat16 hb, lb; split_bf16(v, hb, lb);
        __nv_bfloat16* row = g_Axc + (size_t)b*KG2;
        row[tid]        = hb;
        row[KG + tid]   = hb;
        row[2*KG + tid] = lb;
    }
}

// ---------------- LSTM gates: K-split mma + last-arriver reduce + pointwise. grid (16,7) ----------------
#define LSTM_STG 24576
#define LSTM_SMEM 73728
#define NCHS 6

extern __shared__ char ls_smem[];

__global__ void __launch_bounds__(256, 1) lstm_mma_kernel(int step, int p){
    uint32_t sb = smem_to_u32(ls_smem);
    int tid = threadIdx.x;
    int warp = tid >> 5, lane = tid & 31;
    int wm = warp >> 2, wn = warp & 3;
    int jt = blockIdx.x, ks = blockIdx.y;
    int kbase = ks*(NCHS*64);
    const __nv_bfloat16* Bg = g_Wg2 + (size_t)jt*128*KG2;

    float acc[2][4][4];
    #pragma unroll
    for (int i = 0; i < 2; i++)
        #pragma unroll
        for (int j = 0; j < 4; j++)
            #pragma unroll
            for (int q = 0; q < 4; q++) acc[i][j][q] = 0.f;

#define LLOAD(s, kc) { \
    uint32_t base_ = sb + (uint32_t)(s)*LSTM_STG; \
    _Pragma("unroll") \
    for (int it = 0; it < 6; it++){ \
        int f = tid + it*256; \
        if (f < 512){ \
            int row = f >> 3, ch = f & 7; \
            cp_async16(base_ + (uint32_t)SWZ(row*128 + ch*16), \
                       g_Axc + (size_t)row*KG2 + (kc) + ch*8); \
        } else { \
            int fb = f - 512; \
            int row = fb >> 3, ch = fb & 7; \
            cp_async16(base_ + 8192u + (uint32_t)SWZ(row*128 + ch*16), \
                       Bg + (size_t)row*KG2 + (kc) + ch*8); \
        } \
    } \
    asm volatile("cp.async.commit_group;" ::: "memory"); \
}

    LLOAD(0, kbase);
    LLOAD(1, kbase + 64);
    LLOAD(2, kbase + 128);

    int lrow = ((lane >> 3) & 1)*8 + (lane & 7);
    int lkb  = (lane >> 4)*16;

    for (int c = 0; c < NCHS; c++){
        asm volatile("cp.async.wait_group 2;" ::: "memory");
        __syncthreads();
        int s = c % 3;
        uint32_t aBase = sb + (uint32_t)s*LSTM_STG;
        uint32_t bBase = aBase + 8192;
        #pragma unroll
        for (int k16 = 0; k16 < 4; k16++){
            int kb = k16*32 + lkb;
            uint32_t a[2][4], bfr[2][4];
            #pragma unroll
            for (int mi = 0; mi < 2; mi++){
                int row = wm*32 + mi*16 + lrow;
                ldmatrix_x4(a[mi][0], a[mi][1], a[mi][2], a[mi][3],
                            aBase + (uint32_t)SWZ(row*128 + kb));
            }
            #pragma unroll
            for (int nh = 0; nh < 2; nh++){
                int row = wn*32 + nh*16 + lrow;
                ldmatrix_x4(bfr[nh][0], bfr[nh][1], bfr[nh][2], bfr[nh][3],
                            bBase + (uint32_t)SWZ(row*128 + kb));
            }
            #pragma unroll
            for (int mi = 0; mi < 2; mi++)
                #pragma unroll
                for (int nj = 0; nj < 4; nj++)
                    mma16816(acc[mi][nj], a[mi], bfr[nj>>1][nj&1], bfr[nj>>1][(nj&1)+2]);
        }
        __syncthreads();
        if (c + 3 < NCHS){
            LLOAD((c + 3) % 3, kbase + (c + 3)*64);
        } else {
            asm volatile("cp.async.commit_group;" ::: "memory");
        }
    }
#undef LLOAD

    float* P = g_part + ((size_t)(jt*NSPL + ks))*8192;
    #pragma unroll
    for (int mi = 0; mi < 2; mi++){
        int rbase = wm*32 + mi*16 + (lane >> 2);
        #pragma unroll
        for (int half = 0; half < 2; half++){
            int r = rbase + half*8;
            #pragma unroll
            for (int nj = 0; nj < 4; nj++){
                int col = wn*32 + nj*8 + (lane & 3)*2;
                float2 v = {acc[mi][nj][half*2], acc[mi][nj][half*2 + 1]};
                *(float2*)&P[r*128 + col] = v;
            }
        }
    }
    __threadfence();
    __syncthreads();
    __shared__ int s_old;
    if (tid == 0) s_old = atomicAdd(&g_cnt[jt], 1);
    __syncthreads();
    if (s_old != NSPL - 1) return;

    __threadfence();
    float* sG = (float*)ls_smem;   // [64][132]
    const float* Pj = g_part + (size_t)jt*NSPL*8192;
    #pragma unroll
    for (int qq = 0; qq < 32; qq++){
        int idx = qq*256 + tid;
        float s = 0.f;
        #pragma unroll
        for (int k2 = 0; k2 < NSPL; k2++)
            s += Pj[k2*8192 + idx];
        sG[(idx >> 7)*132 + (idx & 127)] = s;
    }
    __syncthreads();

    int u0 = jt*32;
    int q = p ^ 1;
    #pragma unroll
    for (int qq = 0; qq < 8; qq++){
        int idx = qq*256 + tid;
        int b = idx >> 5, uu = idx & 31;
        int u = u0 + uu;
        float iv = sG[b*132 +      uu] + g_gb[u];
        float fv = sG[b*132 + 32 + uu] + g_gb[HD + u];
        float gv = sG[b*132 + 64 + uu] + g_gb[2*HD + u];
        float ov = sG[b*132 + 96 + uu] + g_gb[3*HD + u];
        float cp = g_c[p][b*HD + u];
        float cn = sigf(fv)*cp + sigf(iv)*tanhacc(gv);
        float hn = sigf(ov)*tanhacc(cn);
        g_c[q][b*HD + u] = cn;
        g_h[q][b*HD + u] = hn;
        g_H[((size_t)step*Bz + b)*HD + u] = hn;
    }
    if (tid == 0) g_cnt[jt] = 0;
}

// ---------------- proj: E = H @ proj.T, epilogue writes split-concat rows A = [hi|hi|lo] ----------------
__global__ void __launch_bounds__(256) proj_kernel(const float* __restrict__ projw){
    __shared__ __align__(16) float sA[64][33];
    __shared__ __align__(16) float sW[64][33];
    int tid = threadIdx.x;
    int r0 = blockIdx.x*64, a0 = blockIdx.y*64;
    int tx = tid & 15, ty = tid >> 4;
    float acc[4][4] = {};
    for (int kc = 0; kc < HD; kc += 32){
        for (int e = tid; e < 64*32; e += 256){
            int row = e >> 5, col = e & 31;
            sA[row][col] = g_H[(size_t)(r0 + row)*HD + kc + col];
            sW[row][col] = projw[(size_t)(a0 + row)*HD + kc + col];
        }
        __syncthreads();
        #pragma unroll
        for (int k = 0; k < 32; k++){
            float af[4], wf[4];
            #pragma unroll
            for (int i = 0; i < 4; i++) af[i] = sA[ty*4 + i][k];
            #pragma unroll
            for (int j = 0; j < 4; j++) wf[j] = sW[tx*4 + j][k];
            #pragma unroll
            for (int i = 0; i < 4; i++)
                #pragma unroll
                for (int j = 0; j < 4; j++)
                    acc[i][j] += af[i]*wf[j];
        }
        __syncthreads();
    }
    #pragma unroll
    for (int i = 0; i < 4; i++){
        int r = r0 + ty*4 + i;
        __nv_bfloat16* row = g_A2 + (size_t)r*K2;
        #pragma unroll
        for (int jp = 0; jp < 2; jp++){
            float x0 = acc[i][jp*2], x1 = acc[i][jp*2 + 1];
            __nv_bfloat16 h0, l0, h1, l1;
            split_bf16(x0, h0, l0);
            split_bf16(x1, h1, l1);
            uint32_t hv = (uint32_t)__bfloat16_as_ushort(h0) | ((uint32_t)__bfloat16_as_ushort(h1) << 16);
            uint32_t lv = (uint32_t)__bfloat16_as_ushort(l0) | ((uint32_t)__bfloat16_as_ushort(l1) << 16);
            int k = a0 + tx*4 + jp*2;
            *(uint32_t*)(row + k)       = hv;
            *(uint32_t*)(row + 256 + k) = hv;
            *(uint32_t*)(row + 512 + k) = lv;
        }
    }
}

// ---------------- logits: mma.sync bf16 GEMM, K=768, 128x128 tile, cp.async 3-stage ----------------
#define KCH 64
#define STG_BYTES 32768
#define LOGIT_SMEM (3*STG_BYTES)

extern __shared__ char lg_smem[];

__global__ void __launch_bounds__(256, 2) logit_mma_kernel(float* __restrict__ out){
    uint32_t sb = smem_to_u32(lg_smem);
    int tid = threadIdx.x;
    int warp = tid >> 5, lane = tid & 31;
    int wm = warp >> 2, wn = warp & 3;
    int r0 = blockIdx.x*128, v0 = blockIdx.y*128;
    const __nv_bfloat16* Ag = g_A2 + (size_t)r0*K2;
    const __nv_bfloat16* Bg = g_B2 + (size_t)v0*K2;

    float acc[4][4][4];
    #pragma unroll
    for (int i = 0; i < 4; i++)
        #pragma unroll
        for (int j = 0; j < 4; j++)
            #pragma unroll
            for (int q = 0; q < 4; q++) acc[i][j][q] = 0.f;

#define LOAD_STAGE(s, kc) { \
    uint32_t base_ = sb + (uint32_t)(s)*STG_BYTES; \
    _Pragma("unroll") \
    for (int it = 0; it < 8; it++){ \
        int f = tid + it*256; \
        int side = f >> 10, idx = f & 1023; \
        int row = idx >> 3, ch = idx & 7; \
        const __nv_bfloat16* src = (side ? Bg : Ag) + (size_t)row*K2 + (kc) + ch*8; \
        uint32_t off = (uint32_t)(side*16384 + SWZ(row*128 + ch*16)); \
        cp_async16(base_ + off, src); \
    } \
    asm volatile("cp.async.commit_group;" ::: "memory"); \
}

    LOAD_STAGE(0, 0);
    LOAD_STAGE(1, KCH);
    LOAD_STAGE(2, 2*KCH);

    int lrow = ((lane >> 3) & 1)*8 + (lane & 7);
    int lkb  = (lane >> 4)*16;

    for (int c = 0; c < 12; c++){
        asm volatile("cp.async.wait_group 2;" ::: "memory");
        __syncthreads();
        int s = c % 3;
        uint32_t aBase = sb + (uint32_t)s*STG_BYTES;
        uint32_t bBase = aBase + 16384;
        #pragma unroll
        for (int k16 = 0; k16 < 4; k16++){
            int kb = k16*32 + lkb;
            uint32_t a[4][4], bfr[2][4];
            #pragma unroll
            for (int mi = 0; mi < 4; mi++){
                int row = wm*64 + mi*16 + lrow;
                ldmatrix_x4(a[mi][0], a[mi][1], a[mi][2], a[mi][3],
                            aBase + (uint32_t)SWZ(row*128 + kb));
            }
            #pragma unroll
            for (int nh = 0; nh < 2; nh++){
                int row = wn*32 + nh*16 + lrow;
                ldmatrix_x4(bfr[nh][0], bfr[nh][1], bfr[nh][2], bfr[nh][3],
                            bBase + (uint32_t)SWZ(row*128 + kb));
            }
            #pragma unroll
            for (int mi = 0; mi < 4; mi++)
                #pragma unroll
                for (int nj = 0; nj < 4; nj++)
                    mma16816(acc[mi][nj], a[mi], bfr[nj>>1][nj&1], bfr[nj>>1][(nj&1)+2]);
        }
        __syncthreads();
        if (c + 3 < 12){
            LOAD_STAGE((c + 3) % 3, (c + 3)*KCH);
        } else {
            asm volatile("cp.async.commit_group;" ::: "memory");
        }
    }

    #pragma unroll
    for (int mi = 0; mi < 4; mi++){
        int rbase = r0 + wm*64 + mi*16 + (lane >> 2);
        #pragma unroll
        for (int half = 0; half < 2; half++){
            int r = rbase + half*8;
            if (r < RTOT){
                int st = r >> 6, bb = r & 63;
                float* op = out + ((size_t)bb*Ss + st)*VOC;
                #pragma unroll
                for (int nj = 0; nj < 4; nj++){
                    int v = v0 + wn*32 + nj*8 + (lane & 3)*2;
                    if (v < VOC){
                        float2 val = {acc[mi][nj][half*2], acc[mi][nj][half*2 + 1]};
                        *(float2*)(op + v) = val;
                    }
                }
            }
        }
    }
#undef LOAD_STAGE
}

// ---------------- launch ----------------
extern "C" void kernel_launch(void* const* d_in, const int* in_sizes, int n_in,
                              void* d_out, int out_size){
    const float* V     = (const float*)d_in[0];
    const int*   y     = (const int*)  d_in[1];
    const float* embed = (const float*)d_in[2];
    const float* Ww    = (const float*)d_in[3];
    const float* Wb    = (const float*)d_in[4];
    const float* Uw    = (const float*)d_in[5];
    const float* Ub    = (const float*)d_in[6];
    const float* vw    = (const float*)d_in[7];
    const float* vb    = (const float*)d_in[8];
    const float* Wih   = (const float*)d_in[9];
    const float* Whh   = (const float*)d_in[10];
    const float* bih   = (const float*)d_in[11];
    const float* bhh   = (const float*)d_in[12];
    const float* projw = (const float*)d_in[13];
    float* out = (float*)d_out;

    cudaFuncSetAttribute(logit_mma_kernel,
                         cudaFuncAttributeMaxDynamicSharedMemorySize, LOGIT_SMEM);
    cudaFuncSetAttribute(lstm_mma_kernel,
                         cudaFuncAttributeMaxDynamicSharedMemorySize, LSTM_SMEM);

    // launch #4 = attn_kernel (ncu profiles #4)
    uv_kernel<<<dim3(Bz, 7), 256>>>(V, Uw, Ub);                                   // 1
    prep_w_kernel<<<2184, 256>>>(Wih, Whh, Ww, bih, bhh);                         // 2
    conv_embed_kernel<<<(VOC*EM)/(256*4), 256>>>(embed);                          // 3
    attn_kernel<<<dim3(Bz, NSPLA), 1024>>>(y, embed, Wb, vw, vb, 0, 0);           // 4 <- profiled
    lstm_mma_kernel<<<dim3(16, NSPL), 256, LSTM_SMEM>>>(0, 0);                    // 5

    for (int j = 1; j < Ss; j++){
        int p = j & 1;
        attn_kernel<<<dim3(Bz, NSPLA), 1024>>>(y, embed, Wb, vw, vb, j, p);
        lstm_mma_kernel<<<dim3(16, NSPL), 256, LSTM_SMEM>>>(j, p);
    }

    proj_kernel<<<dim3(Ss, 4), 256>>>(projw);
    logit_mma_kernel<<<dim3(RP/128, VOCP/128), 256, LOGIT_SMEM>>>(out);
}

// round 15
// speedup vs baseline: 1.1301x; 1.1301x over previous
#include <cuda_runtime.h>
#include <cuda_bf16.h>
#include <cuda_fp16.h>
#include <math.h>
#include <cstdint>

#define Bz 64
#define Nn 196
#define Tt 32
#define Ss 31
#define VD 128
#define EM 256
#define AT 256
#define HD 512
#define VOC 30000
#define VOCP 30080
#define KX 384      // EM + VD
#define KG 896      // EM + VD + HD
#define JG 2048     // 4*HD
#define RTOT 1984   // Ss*Bz
#define RP 2048
#define K2 768      // logit split-concat K
#define KG2 2688    // lstm split-concat K = 3*896
#define NSPL 7      // lstm K-splits
#define NSPLA 3     // attn n-splits (66/66/64)

typedef unsigned long long ULL;

// ---------------- scratch (device globals; zero-initialized, no allocation) ----------------
__device__ float g_h[2][Bz*HD];
__device__ float g_c[2][Bz*HD];
__device__ float g_H[Ss*Bz*HD];
__device__ float g_WwT[HD*AT];                 // Ww transposed [k][a]
__device__ float g_gb[JG];                     // bih + bhh
__device__ float g_part[16*NSPL*64*128];       // lstm partial gates
__device__ int   g_cnt[16];                    // lstm arrival counters (reset in-kernel)
__device__ float g_attp[Bz*NSPLA*132];         // attn partials: {ctx[128], m, s}
__device__ int   g_acnt[Bz];                   // attn ctx arrival counters (reset in-kernel)
__device__ float g_whp[Bz*NSPLA*AT];           // Wh k-slice partials
__device__ int   g_wcnt[Bz];                   // Wh spin counters (monotonic per replay; reset in prep)
__device__ __half g_UVh[Bz*Nn*AT];             // UV in fp16 (6.4MB)
__device__ __half g_Vh[Bz*Nn*VD];              // V copy in fp16 (3.2MB)
__device__ __nv_bfloat16 g_Axc[Bz*KG2];        // per-step xc rows [hi|hi|lo]
__device__ __nv_bfloat16 g_Wg2[JG*KG2];        // gate-interleaved weight rows [hi|lo|hi]
__device__ __nv_bfloat16 g_A2[RP*K2];          // E split-concat rows [hi|hi|lo]; pad rows stay 0
__device__ __nv_bfloat16 g_B2[VOCP*K2];        // embed split-concat rows [hi|lo|hi]; pad rows stay 0

// ---------------- helpers ----------------
__device__ __forceinline__ float sigf(float x){ return __fdividef(1.0f, 1.0f + __expf(-x)); }
__device__ __forceinline__ float tanhacc(float x){
    return __fdividef(2.0f, 1.0f + __expf(-2.0f*x)) - 1.0f;
}
__device__ __forceinline__ __half2 htanh2(__half2 x){
    uint32_t r, xi = *(uint32_t*)&x;
    asm("tanh.approx.f16x2 %0, %1;" : "=r"(r) : "r"(xi));
    return *(__half2*)&r;
}
__device__ __forceinline__ uint32_t smem_to_u32(const void* smem_ptr){
    uint32_t addr;
    asm("{ .reg .u64 tmp; cvta.to.shared.u64 tmp, %1; cvt.u32.u64 %0, tmp; }"
        : "=r"(addr) : "l"(smem_ptr));
    return addr;
}
#define SWZ(o) ((o) ^ (((o) >> 3) & 0x70))

__device__ __forceinline__ void ldmatrix_x4(uint32_t& r0, uint32_t& r1, uint32_t& r2, uint32_t& r3,
                                            uint32_t addr){
    asm volatile("ldmatrix.sync.aligned.m8n8.x4.shared.b16 {%0,%1,%2,%3}, [%4];"
                 : "=r"(r0), "=r"(r1), "=r"(r2), "=r"(r3) : "r"(addr));
}
__device__ __forceinline__ void mma16816(float* d, const uint32_t* a, uint32_t b0, uint32_t b1){
    asm volatile("mma.sync.aligned.m16n8k16.row.col.f32.bf16.bf16.f32 "
                 "{%0,%1,%2,%3}, {%4,%5,%6,%7}, {%8,%9}, {%0,%1,%2,%3};"
                 : "+f"(d[0]), "+f"(d[1]), "+f"(d[2]), "+f"(d[3])
                 : "r"(a[0]), "r"(a[1]), "r"(a[2]), "r"(a[3]), "r"(b0), "r"(b1));
}
__device__ __forceinline__ void cp_async16(uint32_t dst, const void* src){
    asm volatile("cp.async.cg.shared.global [%0], [%1], 16;" :: "r"(dst), "l"(src) : "memory");
}
__device__ __forceinline__ void split_bf16(float x, __nv_bfloat16& h, __nv_bfloat16& l){
    h = __float2bfloat16(x);
    l = __float2bfloat16(x - __bfloat162float(h));
}

// ---------------- embed -> split-concat bf16 rows: B = [hi|lo|hi] ----------------
__global__ void __launch_bounds__(256) conv_embed_kernel(const float* __restrict__ embed){
    size_t i = ((size_t)blockIdx.x*256 + threadIdx.x)*4;
    size_t v = i / EM;
    int k = (int)(i % EM);
    float4 x = *(const float4*)(embed + i);
    float xs[4] = {x.x, x.y, x.z, x.w};
    unsigned short h[4], l[4];
    #pragma unroll
    for (int j = 0; j < 4; j++){
        __nv_bfloat16 hb, lb; split_bf16(xs[j], hb, lb);
        h[j] = __bfloat16_as_ushort(hb);
        l[j] = __bfloat16_as_ushort(lb);
    }
    uint2 hv, lv;
    hv.x = (uint32_t)h[0] | ((uint32_t)h[1] << 16);
    hv.y = (uint32_t)h[2] | ((uint32_t)h[3] << 16);
    lv.x = (uint32_t)l[0] | ((uint32_t)l[1] << 16);
    lv.y = (uint32_t)l[2] | ((uint32_t)l[3] << 16);
    __nv_bfloat16* row = g_B2 + v*K2;
    *(uint2*)(row + k)       = hv;
    *(uint2*)(row + 256 + k) = lv;
    *(uint2*)(row + 512 + k) = hv;
}

// ---------------- one-shot prep: Wg2 rows + misc + WwT transpose ----------------
__global__ void __launch_bounds__(256) prep_w_kernel(const float* __restrict__ Wih,
                                                     const float* __restrict__ Whh,
                                                     const float* __restrict__ Ww,
                                                     const float* __restrict__ bih,
                                                     const float* __restrict__ bhh){
    int bx = blockIdx.x, tid = threadIdx.x;
    if (bx < JG){
        int tile = bx >> 7;
        int within = bx & 127;
        int gate = within >> 5;
        int uu = within & 31;
        int j = gate*HD + tile*32 + uu;
        __nv_bfloat16* row = g_Wg2 + (size_t)bx*KG2;
        for (int k = tid; k < KG; k += 256){
            float w = (k < KX) ? Wih[(size_t)j*KX + k] : Whh[(size_t)j*HD + (k - KX)];
            __nv_bfloat16 hb, lb; split_bf16(w, hb, lb);
            row[k]        = hb;
            row[KG + k]   = lb;
            row[2*KG + k] = hb;
        }
    } else if (bx < JG + 8){
        int bb = bx - JG;
        int idx = bb*256 + tid;           // 0..2047
        g_gb[idx] = bih[idx] + bhh[idx];
        if (idx < Bz) g_wcnt[idx] = 0;    // reset Wh spin counters each replay
        #pragma unroll
        for (int i = 0; i < 16; i++){
            int z = idx*16 + i;
            g_h[0][z] = 0.f;
            g_c[0][z] = 0.f;
        }
    } else {
        __shared__ float t[32][33];
        int bx2 = bx - (JG + 8);
        int a0 = (bx2 & 7)*32;
        int k0 = (bx2 >> 3)*32;
        int tx = tid & 31, ty = tid >> 5;
        #pragma unroll
        for (int i = 0; i < 4; i++)
            t[ty + i*8][tx] = Ww[(size_t)(a0 + ty + i*8)*HD + k0 + tx];
        __syncthreads();
        #pragma unroll
        for (int i = 0; i < 4; i++)
            g_WwT[(size_t)(k0 + ty + i*8)*AT + a0 + tx] = t[tx][ty + i*8];
    }
}

// ---------------- UV (writes fp16 UV + fp16 V copy) ----------------
__global__ void __launch_bounds__(256) uv_kernel(const float* __restrict__ V,
                                                 const float* __restrict__ Uw,
                                                 const float* __restrict__ Ub){
    int b = blockIdx.x;
    int n0 = blockIdx.y * 32;
    int tid = threadIdx.x;
    __shared__ __align__(16) float sV[32][VD];
    for (int e = tid; e < 32*VD; e += 256){
        int n = n0 + (e / VD);
        float v = (n < Nn) ? V[((size_t)b*Nn + n)*VD + (e % VD)] : 0.f;
        sV[e / VD][e % VD] = v;
        if (n < Nn) g_Vh[((size_t)b*Nn + n)*VD + (e % VD)] = __float2half_rn(v);
    }
    __syncthreads();
    int a = tid;
    float acc[32];
    #pragma unroll
    for (int n = 0; n < 32; n++) acc[n] = 0.f;
    for (int kc = 0; kc < VD; kc += 16){
        float u[16];
        #pragma unroll
        for (int i = 0; i < 16; i += 4)
            *(float4*)&u[i] = *(const float4*)&Uw[a*VD + kc + i];
        #pragma unroll
        for (int n = 0; n < 32; n++){
            #pragma unroll
            for (int k = 0; k < 16; k++)
                acc[n] += u[k] * sV[n][kc + k];
        }
    }
    float ub = Ub[a];
    #pragma unroll
    for (int n = 0; n < 32; n++){
        int nn = n0 + n;
        if (nn < Nn) g_UVh[((size_t)b*Nn + nn)*AT + a] = __float2half_rn(acc[n] + ub);
    }
}

// ---------------- fused Wh + attention (flash n-split, f16x2 tanh). grid (64,3), 1024 thr, 2 CTA/SM ----------------
__global__ void __launch_bounds__(1024, 2) attn_kernel(const int* __restrict__ y,
                                                       const float* __restrict__ embed,
                                                       const float* __restrict__ Wb,
                                                       const float* __restrict__ vw,
                                                       const float* __restrict__ vb,
                                                       int step, int p){
    __shared__ __align__(16) float sh[HD];
    __shared__ __align__(16) float sP[1024];
    __shared__ __align__(16) __half2 sWh2[AT/2];
    __shared__ __align__(16) float sv[AT];
    __shared__ __align__(16) float se[68];
    __shared__ __align__(16) float sred[32];
    __shared__ __align__(16) float s_sc[4];
    __shared__ __align__(16) float sctx[VD];
    __shared__ __align__(16) float4 sc4[32][32];
    __shared__ int s_old;

    int b = blockIdx.x, sp = blockIdx.y, tid = threadIdx.x;
    int warp = tid >> 5, lane = tid & 31;
    int n0 = sp*66;
    int n1 = (sp == NSPLA-1) ? Nn : n0 + 66;
    int cnt = n1 - n0;

    if (tid < HD) sh[tid] = g_h[p][b*HD + tid];
    if (tid < AT) sv[tid] = vw[tid];
    __syncthreads();

    // ---- phase 0: Wh k-slice partial. k-range [sp*171, ...], all 256 a
    {
        int k0 = sp*171;
        int k1 = (sp == NSPLA-1) ? HD : k0 + 171;
        int a = tid & 255, kq = tid >> 8;
        float acc = 0.f;
        for (int k = k0 + kq; k < k1; k += 4)
            acc += sh[k] * g_WwT[(size_t)k*AT + a];
        sP[tid] = acc;
    }
    __syncthreads();
    if (tid < AT)
        g_whp[(size_t)(b*NSPLA + sp)*AT + tid] =
            sP[tid] + sP[256 + tid] + sP[512 + tid] + sP[768 + tid];
    __threadfence();
    __syncthreads();
    if (tid == 0){
        atomicAdd(&g_wcnt[b], 1);
        int target = NSPLA*(step + 1);     // monotonic within one replay
        while (atomicAdd(&g_wcnt[b], 0) < target){ __nanosleep(64); }
    }
    __syncthreads();
    __threadfence();
    if (tid < AT/2){
        const float* W0 = g_whp + (size_t)b*NSPLA*AT;
        int a0 = 2*tid, a1 = 2*tid + 1;
        float x0 = W0[a0] + W0[AT + a0] + W0[2*AT + a0] + Wb[a0];
        float x1 = W0[a1] + W0[AT + a1] + W0[2*AT + a1] + Wb[a1];
        sWh2[tid] = __floats2half2_rn(x0, x1);
    }
    __syncthreads();

    // ---- local e_n = v . tanh(Wh + UV[n]) + vb   (f16x2 tanh: 1 MUFU per pair)
    float vbias = vb[0];
    for (int n = n0 + warp; n < n1; n += 32){
        const uint32_t* uvp = (const uint32_t*)(g_UVh + ((size_t)b*Nn + n)*AT);
        float pz = 0.f;
        #pragma unroll
        for (int j = 0; j < 4; j++){
            int idx = lane + j*32;
            uint32_t pa = uvp[idx];
            __half2 s2 = __hadd2(sWh2[idx], *(__half2*)&pa);
            float2 t = __half22float2(htanh2(s2));
            float2 v2 = *(const float2*)&sv[2*idx];
            pz += t.x*v2.x + t.y*v2.y;
        }
        #pragma unroll
        for (int o = 16; o; o >>= 1) pz += __shfl_xor_sync(0xffffffffu, pz, o);
        if (lane == 0) se[n - n0] = pz + vbias;
    }
    __syncthreads();

    // ---- local max + exp + sum
    float m = (tid < cnt) ? se[tid] : -1e30f;
    #pragma unroll
    for (int o = 16; o; o >>= 1) m = fmaxf(m, __shfl_xor_sync(0xffffffffu, m, o));
    if (lane == 0) sred[warp] = m;
    __syncthreads();
    if (tid == 0){
        float mm = sred[0];
        #pragma unroll
        for (int i = 1; i < 3; i++) mm = fmaxf(mm, sred[i]);
        s_sc[0] = mm;
    }
    __syncthreads();
    float mloc = s_sc[0];
    float ex = (tid < cnt) ? __expf(se[tid] - mloc) : 0.f;
    if (tid < cnt) se[tid] = ex;
    float sum = ex;
    #pragma unroll
    for (int o = 16; o; o >>= 1) sum += __shfl_xor_sync(0xffffffffu, sum, o);
    if (lane == 0) sred[warp] = sum;
    __syncthreads();
    if (tid == 0){
        s_sc[1] = sred[0] + sred[1] + sred[2];
    }
    __syncthreads();

    // ---- partial ctx
    float4 a4 = {0.f, 0.f, 0.f, 0.f};
    for (int n = n0 + warp; n < n1; n += 32){
        float w = se[n - n0];
        uint2 pv = *(const uint2*)(g_Vh + ((size_t)b*Nn + n)*VD + lane*4);
        float2 lo = __half22float2(*(__half2*)&pv.x);
        float2 hi = __half22float2(*(__half2*)&pv.y);
        a4.x += w*lo.x; a4.y += w*lo.y; a4.z += w*hi.x; a4.w += w*hi.y;
    }
    sc4[warp][lane] = a4;
    __syncthreads();
    #pragma unroll
    for (int off = 16; off; off >>= 1){
        if (warp < off){
            float4 x = sc4[warp][lane], y4 = sc4[warp + off][lane];
            x.x += y4.x; x.y += y4.y; x.z += y4.z; x.w += y4.w;
            sc4[warp][lane] = x;
        }
        __syncthreads();
    }

    // ---- write partial {ctx[128], m, s}
    float* P = g_attp + (size_t)(b*NSPLA + sp)*132;
    if (tid < 32){
        float4 cv = sc4[0][tid];
        *(float4*)&P[tid*4] = cv;
    }
    if (tid == 32) P[128] = mloc;
    if (tid == 33) P[129] = s_sc[1];
    __threadfence();
    __syncthreads();
    if (tid == 0) s_old = atomicAdd(&g_acnt[b], 1);
    __syncthreads();
    if (s_old != NSPLA - 1) return;

    // ---- last arriver: combine partials + xc epilogue
    __threadfence();
    const float* P0 = g_attp + (size_t)b*NSPLA*132;
    if (tid == 0){
        float m0 = P0[128], m1 = P0[132 + 128], m2 = P0[264 + 128];
        float mg = fmaxf(m0, fmaxf(m1, m2));
        float w0 = __expf(m0 - mg), w1 = __expf(m1 - mg), w2 = __expf(m2 - mg);
        float tot = P0[129]*w0 + P0[132 + 129]*w1 + P0[264 + 129]*w2;
        s_sc[0] = w0; s_sc[1] = w1; s_sc[2] = w2; s_sc[3] = 1.0f / tot;
        g_acnt[b] = 0;
    }
    __syncthreads();
    if (tid < VD){
        float w0 = s_sc[0], w1 = s_sc[1], w2 = s_sc[2], inv = s_sc[3];
        float cv = P0[tid]*w0 + P0[132 + tid]*w1 + P0[264 + tid]*w2;
        sctx[tid] = cv * inv;
    }
    __syncthreads();

    if (tid < KG){
        int tok = y[b*Tt + step];
        float v;
        if (tid < EM)      v = embed[(size_t)tok*EM + tid];
        else if (tid < KX) v = sctx[tid - EM];
        else               v = sh[tid - KX];
        __nv_bfloat16 hb, lb; split_bf16(v, hb, lb);
        __nv_bfloat16* row = g_Axc + (size_t)b*KG2;
        row[tid]        = hb;
        row[KG + tid]   = hb;
        row[2*KG + tid] = lb;
    }
}

// ---------------- LSTM gates: K-split mma + last-arriver reduce + pointwise. grid (16,7) ----------------
#define LSTM_STG 24576
#define LSTM_SMEM 73728
#define NCHS 6

extern __shared__ char ls_smem[];

__global__ void __launch_bounds__(256, 1) lstm_mma_kernel(int step, int p){
    uint32_t sb = smem_to_u32(ls_smem);
    int tid = threadIdx.x;
    int warp = tid >> 5, lane = tid & 31;
    int wm = warp >> 2, wn = warp & 3;
    int jt = blockIdx.x, ks = blockIdx.y;
    int kbase = ks*(NCHS*64);
    const __nv_bfloat16* Bg = g_Wg2 + (size_t)jt*128*KG2;

    float acc[2][4][4];
    #pragma unroll
    for (int i = 0; i < 2; i++)
        #pragma unroll
        for (int j = 0; j < 4; j++)
            #pragma unroll
            for (int q = 0; q < 4; q++) acc[i][j][q] = 0.f;

#define LLOAD(s, kc) { \
    uint32_t base_ = sb + (uint32_t)(s)*LSTM_STG; \
    _Pragma("unroll") \
    for (int it = 0; it < 6; it++){ \
        int f = tid + it*256; \
        if (f < 512){ \
            int row = f >> 3, ch = f & 7; \
            cp_async16(base_ + (uint32_t)SWZ(row*128 + ch*16), \
                       g_Axc + (size_t)row*KG2 + (kc) + ch*8); \
        } else { \
            int fb = f - 512; \
            int row = fb >> 3, ch = fb & 7; \
            cp_async16(base_ + 8192u + (uint32_t)SWZ(row*128 + ch*16), \
                       Bg + (size_t)row*KG2 + (kc) + ch*8); \
        } \
    } \
    asm volatile("cp.async.commit_group;" ::: "memory"); \
}

    LLOAD(0, kbase);
    LLOAD(1, kbase + 64);
    LLOAD(2, kbase + 128);

    int lrow = ((lane >> 3) & 1)*8 + (lane & 7);
    int lkb  = (lane >> 4)*16;

    for (int c = 0; c < NCHS; c++){
        asm volatile("cp.async.wait_group 2;" ::: "memory");
        __syncthreads();
        int s = c % 3;
        uint32_t aBase = sb + (uint32_t)s*LSTM_STG;
        uint32_t bBase = aBase + 8192;
        #pragma unroll
        for (int k16 = 0; k16 < 4; k16++){
            int kb = k16*32 + lkb;
            uint32_t a[2][4], bfr[2][4];
            #pragma unroll
            for (int mi = 0; mi < 2; mi++){
                int row = wm*32 + mi*16 + lrow;
                ldmatrix_x4(a[mi][0], a[mi][1], a[mi][2], a[mi][3],
                            aBase + (uint32_t)SWZ(row*128 + kb));
            }
            #pragma unroll
            for (int nh = 0; nh < 2; nh++){
                int row = wn*32 + nh*16 + lrow;
                ldmatrix_x4(bfr[nh][0], bfr[nh][1], bfr[nh][2], bfr[nh][3],
                            bBase + (uint32_t)SWZ(row*128 + kb));
            }
            #pragma unroll
            for (int mi = 0; mi < 2; mi++)
                #pragma unroll
                for (int nj = 0; nj < 4; nj++)
                    mma16816(acc[mi][nj], a[mi], bfr[nj>>1][nj&1], bfr[nj>>1][(nj&1)+2]);
        }
        __syncthreads();
        if (c + 3 < NCHS){
            LLOAD((c + 3) % 3, kbase + (c + 3)*64);
        } else {
            asm volatile("cp.async.commit_group;" ::: "memory");
        }
    }
#undef LLOAD

    float* P = g_part + ((size_t)(jt*NSPL + ks))*8192;
    #pragma unroll
    for (int mi = 0; mi < 2; mi++){
        int rbase = wm*32 + mi*16 + (lane >> 2);
        #pragma unroll
        for (int half = 0; half < 2; half++){
            int r = rbase + half*8;
            #pragma unroll
            for (int nj = 0; nj < 4; nj++){
                int col = wn*32 + nj*8 + (lane & 3)*2;
                float2 v = {acc[mi][nj][half*2], acc[mi][nj][half*2 + 1]};
                *(float2*)&P[r*128 + col] = v;
            }
        }
    }
    __threadfence();
    __syncthreads();
    __shared__ int s_old;
    if (tid == 0) s_old = atomicAdd(&g_cnt[jt], 1);
    __syncthreads();
    if (s_old != NSPL - 1) return;

    __threadfence();
    float* sG = (float*)ls_smem;   // [64][132]
    const float* Pj = g_part + (size_t)jt*NSPL*8192;
    #pragma unroll
    for (int qq = 0; qq < 32; qq++){
        int idx = qq*256 + tid;
        float s = 0.f;
        #pragma unroll
        for (int k2 = 0; k2 < NSPL; k2++)
            s += Pj[k2*8192 + idx];
        sG[(idx >> 7)*132 + (idx & 127)] = s;
    }
    __syncthreads();

    int u0 = jt*32;
    int q = p ^ 1;
    #pragma unroll
    for (int qq = 0; qq < 8; qq++){
        int idx = qq*256 + tid;
        int b = idx >> 5, uu = idx & 31;
        int u = u0 + uu;
        float iv = sG[b*132 +      uu] + g_gb[u];
        float fv = sG[b*132 + 32 + uu] + g_gb[HD + u];
        float gv = sG[b*132 + 64 + uu] + g_gb[2*HD + u];
        float ov = sG[b*132 + 96 + uu] + g_gb[3*HD + u];
        float cp = g_c[p][b*HD + u];
        float cn = sigf(fv)*cp + sigf(iv)*tanhacc(gv);
        float hn = sigf(ov)*tanhacc(cn);
        g_c[q][b*HD + u] = cn;
        g_h[q][b*HD + u] = hn;
        g_H[((size_t)step*Bz + b)*HD + u] = hn;
    }
    if (tid == 0) g_cnt[jt] = 0;
}

// ---------------- proj: E = H @ proj.T, epilogue writes split-concat rows A = [hi|hi|lo] ----------------
__global__ void __launch_bounds__(256) proj_kernel(const float* __restrict__ projw){
    __shared__ __align__(16) float sA[64][33];
    __shared__ __align__(16) float sW[64][33];
    int tid = threadIdx.x;
    int r0 = blockIdx.x*64, a0 = blockIdx.y*64;
    int tx = tid & 15, ty = tid >> 4;
    float acc[4][4] = {};
    for (int kc = 0; kc < HD; kc += 32){
        for (int e = tid; e < 64*32; e += 256){
            int row = e >> 5, col = e & 31;
            sA[row][col] = g_H[(size_t)(r0 + row)*HD + kc + col];
            sW[row][col] = projw[(size_t)(a0 + row)*HD + kc + col];
        }
        __syncthreads();
        #pragma unroll
        for (int k = 0; k < 32; k++){
            float af[4], wf[4];
            #pragma unroll
            for (int i = 0; i < 4; i++) af[i] = sA[ty*4 + i][k];
            #pragma unroll
            for (int j = 0; j < 4; j++) wf[j] = sW[tx*4 + j][k];
            #pragma unroll
            for (int i = 0; i < 4; i++)
                #pragma unroll
                for (int j = 0; j < 4; j++)
                    acc[i][j] += af[i]*wf[j];
        }
        __syncthreads();
    }
    #pragma unroll
    for (int i = 0; i < 4; i++){
        int r = r0 + ty*4 + i;
        __nv_bfloat16* row = g_A2 + (size_t)r*K2;
        #pragma unroll
        for (int jp = 0; jp < 2; jp++){
            float x0 = acc[i][jp*2], x1 = acc[i][jp*2 + 1];
            __nv_bfloat16 h0, l0, h1, l1;
            split_bf16(x0, h0, l0);
            split_bf16(x1, h1, l1);
            uint32_t hv = (uint32_t)__bfloat16_as_ushort(h0) | ((uint32_t)__bfloat16_as_ushort(h1) << 16);
            uint32_t lv = (uint32_t)__bfloat16_as_ushort(l0) | ((uint32_t)__bfloat16_as_ushort(l1) << 16);
            int k = a0 + tx*4 + jp*2;
            *(uint32_t*)(row + k)       = hv;
            *(uint32_t*)(row + 256 + k) = hv;
            *(uint32_t*)(row + 512 + k) = lv;
        }
    }
}

// ---------------- logits: mma.sync bf16 GEMM, K=768, 128x128 tile, cp.async 3-stage ----------------
#define KCH 64
#define STG_BYTES 32768
#define LOGIT_SMEM (3*STG_BYTES)

extern __shared__ char lg_smem[];

__global__ void __launch_bounds__(256, 2) logit_mma_kernel(float* __restrict__ out){
    uint32_t sb = smem_to_u32(lg_smem);
    int tid = threadIdx.x;
    int warp = tid >> 5, lane = tid & 31;
    int wm = warp >> 2, wn = warp & 3;
    int r0 = blockIdx.x*128, v0 = blockIdx.y*128;
    const __nv_bfloat16* Ag = g_A2 + (size_t)r0*K2;
    const __nv_bfloat16* Bg = g_B2 + (size_t)v0*K2;

    float acc[4][4][4];
    #pragma unroll
    for (int i = 0; i < 4; i++)
        #pragma unroll
        for (int j = 0; j < 4; j++)
            #pragma unroll
            for (int q = 0; q < 4; q++) acc[i][j][q] = 0.f;

#define LOAD_STAGE(s, kc) { \
    uint32_t base_ = sb + (uint32_t)(s)*STG_BYTES; \
    _Pragma("unroll") \
    for (int it = 0; it < 8; it++){ \
        int f = tid + it*256; \
        int side = f >> 10, idx = f & 1023; \
        int row = idx >> 3, ch = idx & 7; \
        const __nv_bfloat16* src = (side ? Bg : Ag) + (size_t)row*K2 + (kc) + ch*8; \
        uint32_t off = (uint32_t)(side*16384 + SWZ(row*128 + ch*16)); \
        cp_async16(base_ + off, src); \
    } \
    asm volatile("cp.async.commit_group;" ::: "memory"); \
}

    LOAD_STAGE(0, 0);
    LOAD_STAGE(1, KCH);
    LOAD_STAGE(2, 2*KCH);

    int lrow = ((lane >> 3) & 1)*8 + (lane & 7);
    int lkb  = (lane >> 4)*16;

    for (int c = 0; c < 12; c++){
        asm volatile("cp.async.wait_group 2;" ::: "memory");
        __syncthreads();
        int s = c % 3;
        uint32_t aBase = sb + (uint32_t)s*STG_BYTES;
        uint32_t bBase = aBase + 16384;
        #pragma unroll
        for (int k16 = 0; k16 < 4; k16++){
            int kb = k16*32 + lkb;
            uint32_t a[4][4], bfr[2][4];
            #pragma unroll
            for (int mi = 0; mi < 4; mi++){
                int row = wm*64 + mi*16 + lrow;
                ldmatrix_x4(a[mi][0], a[mi][1], a[mi][2], a[mi][3],
                            aBase + (uint32_t)SWZ(row*128 + kb));
            }
            #pragma unroll
            for (int nh = 0; nh < 2; nh++){
                int row = wn*32 + nh*16 + lrow;
                ldmatrix_x4(bfr[nh][0], bfr[nh][1], bfr[nh][2], bfr[nh][3],
                            bBase + (uint32_t)SWZ(row*128 + kb));
            }
            #pragma unroll
            for (int mi = 0; mi < 4; mi++)
                #pragma unroll
                for (int nj = 0; nj < 4; nj++)
                    mma16816(acc[mi][nj], a[mi], bfr[nj>>1][nj&1], bfr[nj>>1][(nj&1)+2]);
        }
        __syncthreads();
        if (c + 3 < 12){
            LOAD_STAGE((c + 3) % 3, (c + 3)*KCH);
        } else {
            asm volatile("cp.async.commit_group;" ::: "memory");
        }
    }

    #pragma unroll
    for (int mi = 0; mi < 4; mi++){
        int rbase = r0 + wm*64 + mi*16 + (lane >> 2);
        #pragma unroll
        for (int half = 0; half < 2; half++){
            int r = rbase + half*8;
            if (r < RTOT){
                int st = r >> 6, bb = r & 63;
                float* op = out + ((size_t)bb*Ss + st)*VOC;
                #pragma unroll
                for (int nj = 0; nj < 4; nj++){
                    int v = v0 + wn*32 + nj*8 + (lane & 3)*2;
                    if (v < VOC){
                        float2 val = {acc[mi][nj][half*2], acc[mi][nj][half*2 + 1]};
                        *(float2*)(op + v) = val;
                    }
                }
            }
        }
    }
#undef LOAD_STAGE
}

// ---------------- launch ----------------
extern "C" void kernel_launch(void* const* d_in, const int* in_sizes, int n_in,
                              void* d_out, int out_size){
    const float* V     = (const float*)d_in[0];
    const int*   y     = (const int*)  d_in[1];
    const float* embed = (const float*)d_in[2];
    const float* Ww    = (const float*)d_in[3];
    const float* Wb    = (const float*)d_in[4];
    const float* Uw    = (const float*)d_in[5];
    const float* Ub    = (const float*)d_in[6];
    const float* vw    = (const float*)d_in[7];
    const float* vb    = (const float*)d_in[8];
    const float* Wih   = (const float*)d_in[9];
    const float* Whh   = (const float*)d_in[10];
    const float* bih   = (const float*)d_in[11];
    const float* bhh   = (const float*)d_in[12];
    const float* projw = (const float*)d_in[13];
    float* out = (float*)d_out;

    cudaFuncSetAttribute(logit_mma_kernel,
                         cudaFuncAttributeMaxDynamicSharedMemorySize, LOGIT_SMEM);
    cudaFuncSetAttribute(lstm_mma_kernel,
                         cudaFuncAttributeMaxDynamicSharedMemorySize, LSTM_SMEM);

    // launch #4 = attn_kernel (ncu profiles #4)
    uv_kernel<<<dim3(Bz, 7), 256>>>(V, Uw, Ub);                                   // 1
    prep_w_kernel<<<2184, 256>>>(Wih, Whh, Ww, bih, bhh);                         // 2
    conv_embed_kernel<<<(VOC*EM)/(256*4), 256>>>(embed);                          // 3
    attn_kernel<<<dim3(Bz, NSPLA), 1024>>>(y, embed, Wb, vw, vb, 0, 0);           // 4 <- profiled
    lstm_mma_kernel<<<dim3(16, NSPL), 256, LSTM_SMEM>>>(0, 0);                    // 5

    for (int j = 1; j < Ss; j++){
        int p = j & 1;
        attn_kernel<<<dim3(Bz, NSPLA), 1024>>>(y, embed, Wb, vw, vb, j, p);
        lstm_mma_kernel<<<dim3(16, NSPL), 256, LSTM_SMEM>>>(j, p);
    }

    proj_kernel<<<dim3(Ss, 4), 256>>>(projw);
    logit_mma_kernel<<<dim3(RP/128, VOCP/128), 256, LOGIT_SMEM>>>(out);
}

// round 16
// speedup vs baseline: 1.2057x; 1.0668x over previous
#include <cuda_runtime.h>
#include <cuda_bf16.h>
#include <cuda_fp16.h>
#include <math.h>
#include <cstdint>

#define Bz 64
#define Nn 196
#define Tt 32
#define Ss 31
#define VD 128
#define EM 256
#define AT 256
#define HD 512
#define VOC 30000
#define VOCP 30080
#define KX 384      // EM + VD
#define KG 896      // EM + VD + HD
#define JG 2048     // 4*HD
#define RTOT 1984   // Ss*Bz
#define RP 2048
#define K2 512      // logit fp16 2-term split K: A=[hi|hi], B=[hi|lo]
#define KG2 2688    // lstm split-concat K = 3*896
#define NSPL 7      // lstm K-splits
#define NSPLA 3     // attn n-splits (66/66/64)

typedef unsigned long long ULL;

// ---------------- scratch (device globals; zero-initialized, no allocation) ----------------
__device__ float g_h[2][Bz*HD];
__device__ float g_c[2][Bz*HD];
__device__ float g_H[Ss*Bz*HD];
__device__ float g_WwT[HD*AT];                 // Ww transposed [k][a]
__device__ float g_gb[JG];                     // bih + bhh
__device__ float g_part[16*NSPL*64*128];       // lstm partial gates
__device__ int   g_cnt[16];                    // lstm arrival counters (reset in-kernel)
__device__ float g_attp[Bz*NSPLA*132];         // attn partials: {ctx[128], m, s}
__device__ int   g_acnt[Bz];                   // attn ctx arrival counters (reset in-kernel)
__device__ float g_whp[Bz*NSPLA*AT];           // Wh k-slice partials
__device__ int   g_wcnt[Bz];                   // Wh spin counters (monotonic per replay; reset in prep)
__device__ __half g_UVh[Bz*Nn*AT];             // UV in fp16 (6.4MB)
__device__ __half g_Vh[Bz*Nn*VD];              // V copy in fp16 (3.2MB)
__device__ __nv_bfloat16 g_Axc[Bz*KG2];        // per-step xc rows [hi|hi|lo]
__device__ __nv_bfloat16 g_Wg2[JG*KG2];        // gate-interleaved weight rows [hi|lo|hi]
__device__ __half g_A2[RP*K2];                 // E fp16 rows [hi|hi]; pad rows stay 0
__device__ __half g_B2[VOCP*K2];               // embed fp16 rows [hi|lo]; pad rows stay 0

// ---------------- helpers ----------------
__device__ __forceinline__ float sigf(float x){ return __fdividef(1.0f, 1.0f + __expf(-x)); }
__device__ __forceinline__ float tanhacc(float x){
    return __fdividef(2.0f, 1.0f + __expf(-2.0f*x)) - 1.0f;
}
__device__ __forceinline__ __half2 htanh2(__half2 x){
    uint32_t r, xi = *(uint32_t*)&x;
    asm("tanh.approx.f16x2 %0, %1;" : "=r"(r) : "r"(xi));
    return *(__half2*)&r;
}
__device__ __forceinline__ uint32_t smem_to_u32(const void* smem_ptr){
    uint32_t addr;
    asm("{ .reg .u64 tmp; cvta.to.shared.u64 tmp, %1; cvt.u32.u64 %0, tmp; }"
        : "=r"(addr) : "l"(smem_ptr));
    return addr;
}
#define SWZ(o) ((o) ^ (((o) >> 3) & 0x70))

__device__ __forceinline__ void ldmatrix_x4(uint32_t& r0, uint32_t& r1, uint32_t& r2, uint32_t& r3,
                                            uint32_t addr){
    asm volatile("ldmatrix.sync.aligned.m8n8.x4.shared.b16 {%0,%1,%2,%3}, [%4];"
                 : "=r"(r0), "=r"(r1), "=r"(r2), "=r"(r3) : "r"(addr));
}
__device__ __forceinline__ void mma16816(float* d, const uint32_t* a, uint32_t b0, uint32_t b1){
    asm volatile("mma.sync.aligned.m16n8k16.row.col.f32.bf16.bf16.f32 "
                 "{%0,%1,%2,%3}, {%4,%5,%6,%7}, {%8,%9}, {%0,%1,%2,%3};"
                 : "+f"(d[0]), "+f"(d[1]), "+f"(d[2]), "+f"(d[3])
                 : "r"(a[0]), "r"(a[1]), "r"(a[2]), "r"(a[3]), "r"(b0), "r"(b1));
}
__device__ __forceinline__ void mma16816h(float* d, const uint32_t* a, uint32_t b0, uint32_t b1){
    asm volatile("mma.sync.aligned.m16n8k16.row.col.f32.f16.f16.f32 "
                 "{%0,%1,%2,%3}, {%4,%5,%6,%7}, {%8,%9}, {%0,%1,%2,%3};"
                 : "+f"(d[0]), "+f"(d[1]), "+f"(d[2]), "+f"(d[3])
                 : "r"(a[0]), "r"(a[1]), "r"(a[2]), "r"(a[3]), "r"(b0), "r"(b1));
}
__device__ __forceinline__ void cp_async16(uint32_t dst, const void* src){
    asm volatile("cp.async.cg.shared.global [%0], [%1], 16;" :: "r"(dst), "l"(src) : "memory");
}
__device__ __forceinline__ void split_bf16(float x, __nv_bfloat16& h, __nv_bfloat16& l){
    h = __float2bfloat16(x);
    l = __float2bfloat16(x - __bfloat162float(h));
}
__device__ __forceinline__ void split_f16(float x, __half& h, __half& l){
    h = __float2half_rn(x);
    l = __float2half_rn(x - __half2float(h));
}

// ---------------- embed -> fp16 split rows: B = [hi|lo] ----------------
__global__ void __launch_bounds__(256) conv_embed_kernel(const float* __restrict__ embed){
    size_t i = ((size_t)blockIdx.x*256 + threadIdx.x)*4;
    size_t v = i / EM;
    int k = (int)(i % EM);
    float4 x = *(const float4*)(embed + i);
    float xs[4] = {x.x, x.y, x.z, x.w};
    unsigned short h[4], l[4];
    #pragma unroll
    for (int j = 0; j < 4; j++){
        __half hb, lb; split_f16(xs[j], hb, lb);
        h[j] = __half_as_ushort(hb);
        l[j] = __half_as_ushort(lb);
    }
    uint2 hv, lv;
    hv.x = (uint32_t)h[0] | ((uint32_t)h[1] << 16);
    hv.y = (uint32_t)h[2] | ((uint32_t)h[3] << 16);
    lv.x = (uint32_t)l[0] | ((uint32_t)l[1] << 16);
    lv.y = (uint32_t)l[2] | ((uint32_t)l[3] << 16);
    __half* row = g_B2 + v*K2;
    *(uint2*)(row + k)       = hv;
    *(uint2*)(row + 256 + k) = lv;
}

// ---------------- one-shot prep: Wg2 rows + misc + WwT transpose ----------------
__global__ void __launch_bounds__(256) prep_w_kernel(const float* __restrict__ Wih,
                                                     const float* __restrict__ Whh,
                                                     const float* __restrict__ Ww,
                                                     const float* __restrict__ bih,
                                                     const float* __restrict__ bhh){
    int bx = blockIdx.x, tid = threadIdx.x;
    if (bx < JG){
        int tile = bx >> 7;
        int within = bx & 127;
        int gate = within >> 5;
        int uu = within & 31;
        int j = gate*HD + tile*32 + uu;
        __nv_bfloat16* row = g_Wg2 + (size_t)bx*KG2;
        for (int k = tid; k < KG; k += 256){
            float w = (k < KX) ? Wih[(size_t)j*KX + k] : Whh[(size_t)j*HD + (k - KX)];
            __nv_bfloat16 hb, lb; split_bf16(w, hb, lb);
            row[k]        = hb;
            row[KG + k]   = lb;
            row[2*KG + k] = hb;
        }
    } else if (bx < JG + 8){
        int bb = bx - JG;
        int idx = bb*256 + tid;           // 0..2047
        g_gb[idx] = bih[idx] + bhh[idx];
        if (idx < Bz) g_wcnt[idx] = 0;    // reset Wh spin counters each replay
        #pragma unroll
        for (int i = 0; i < 16; i++){
            int z = idx*16 + i;
            g_h[0][z] = 0.f;
            g_c[0][z] = 0.f;
        }
    } else {
        __shared__ float t[32][33];
        int bx2 = bx - (JG + 8);
        int a0 = (bx2 & 7)*32;
        int k0 = (bx2 >> 3)*32;
        int tx = tid & 31, ty = tid >> 5;
        #pragma unroll
        for (int i = 0; i < 4; i++)
            t[ty + i*8][tx] = Ww[(size_t)(a0 + ty + i*8)*HD + k0 + tx];
        __syncthreads();
        #pragma unroll
        for (int i = 0; i < 4; i++)
            g_WwT[(size_t)(k0 + ty + i*8)*AT + a0 + tx] = t[tx][ty + i*8];
    }
}

// ---------------- UV (writes fp16 UV + fp16 V copy) ----------------
__global__ void __launch_bounds__(256) uv_kernel(const float* __restrict__ V,
                                                 const float* __restrict__ Uw,
                                                 const float* __restrict__ Ub){
    int b = blockIdx.x;
    int n0 = blockIdx.y * 32;
    int tid = threadIdx.x;
    __shared__ __align__(16) float sV[32][VD];
    for (int e = tid; e < 32*VD; e += 256){
        int n = n0 + (e / VD);
        float v = (n < Nn) ? V[((size_t)b*Nn + n)*VD + (e % VD)] : 0.f;
        sV[e / VD][e % VD] = v;
        if (n < Nn) g_Vh[((size_t)b*Nn + n)*VD + (e % VD)] = __float2half_rn(v);
    }
    __syncthreads();
    int a = tid;
    float acc[32];
    #pragma unroll
    for (int n = 0; n < 32; n++) acc[n] = 0.f;
    for (int kc = 0; kc < VD; kc += 16){
        float u[16];
        #pragma unroll
        for (int i = 0; i < 16; i += 4)
            *(float4*)&u[i] = *(const float4*)&Uw[a*VD + kc + i];
        #pragma unroll
        for (int n = 0; n < 32; n++){
            #pragma unroll
            for (int k = 0; k < 16; k++)
                acc[n] += u[k] * sV[n][kc + k];
        }
    }
    float ub = Ub[a];
    #pragma unroll
    for (int n = 0; n < 32; n++){
        int nn = n0 + n;
        if (nn < Nn) g_UVh[((size_t)b*Nn + nn)*AT + a] = __float2half_rn(acc[n] + ub);
    }
}

// ---------------- fused Wh + attention (flash n-split, f16x2 tanh). grid (64,3), 1024 thr, 2 CTA/SM ----------------
__global__ void __launch_bounds__(1024, 2) attn_kernel(const int* __restrict__ y,
                                                       const float* __restrict__ embed,
                                                       const float* __restrict__ Wb,
                                                       const float* __restrict__ vw,
                                                       const float* __restrict__ vb,
                                                       int step, int p){
    __shared__ __align__(16) float sh[HD];
    __shared__ __align__(16) float sP[1024];
    __shared__ __align__(16) __half2 sWh2[AT/2];
    __shared__ __align__(16) float sv[AT];
    __shared__ __align__(16) float se[68];
    __shared__ __align__(16) float sred[32];
    __shared__ __align__(16) float s_sc[4];
    __shared__ __align__(16) float sctx[VD];
    __shared__ __align__(16) float4 sc4[32][32];
    __shared__ int s_old;

    int b = blockIdx.x, sp = blockIdx.y, tid = threadIdx.x;
    int warp = tid >> 5, lane = tid & 31;
    int n0 = sp*66;
    int n1 = (sp == NSPLA-1) ? Nn : n0 + 66;
    int cnt = n1 - n0;

    if (tid < HD) sh[tid] = g_h[p][b*HD + tid];
    if (tid < AT) sv[tid] = vw[tid];
    __syncthreads();

    // ---- phase 0: Wh k-slice partial
    {
        int k0 = sp*171;
        int k1 = (sp == NSPLA-1) ? HD : k0 + 171;
        int a = tid & 255, kq = tid >> 8;
        float acc = 0.f;
        for (int k = k0 + kq; k < k1; k += 4)
            acc += sh[k] * g_WwT[(size_t)k*AT + a];
        sP[tid] = acc;
    }
    __syncthreads();
    if (tid < AT)
        g_whp[(size_t)(b*NSPLA + sp)*AT + tid] =
            sP[tid] + sP[256 + tid] + sP[512 + tid] + sP[768 + tid];
    __threadfence();
    __syncthreads();
    if (tid == 0){
        atomicAdd(&g_wcnt[b], 1);
        int target = NSPLA*(step + 1);
        while (atomicAdd(&g_wcnt[b], 0) < target){ __nanosleep(64); }
    }
    __syncthreads();
    __threadfence();
    if (tid < AT/2){
        const float* W0 = g_whp + (size_t)b*NSPLA*AT;
        int a0 = 2*tid, a1 = 2*tid + 1;
        float x0 = W0[a0] + W0[AT + a0] + W0[2*AT + a0] + Wb[a0];
        float x1 = W0[a1] + W0[AT + a1] + W0[2*AT + a1] + Wb[a1];
        sWh2[tid] = __floats2half2_rn(x0, x1);
    }
    __syncthreads();

    // ---- local e_n = v . tanh(Wh + UV[n]) + vb
    float vbias = vb[0];
    for (int n = n0 + warp; n < n1; n += 32){
        const uint32_t* uvp = (const uint32_t*)(g_UVh + ((size_t)b*Nn + n)*AT);
        float pz = 0.f;
        #pragma unroll
        for (int j = 0; j < 4; j++){
            int idx = lane + j*32;
            uint32_t pa = uvp[idx];
            __half2 s2 = __hadd2(sWh2[idx], *(__half2*)&pa);
            float2 t = __half22float2(htanh2(s2));
            float2 v2 = *(const float2*)&sv[2*idx];
            pz += t.x*v2.x + t.y*v2.y;
        }
        #pragma unroll
        for (int o = 16; o; o >>= 1) pz += __shfl_xor_sync(0xffffffffu, pz, o);
        if (lane == 0) se[n - n0] = pz + vbias;
    }
    __syncthreads();

    // ---- local max + exp + sum
    float m = (tid < cnt) ? se[tid] : -1e30f;
    #pragma unroll
    for (int o = 16; o; o >>= 1) m = fmaxf(m, __shfl_xor_sync(0xffffffffu, m, o));
    if (lane == 0) sred[warp] = m;
    __syncthreads();
    if (tid == 0){
        float mm = sred[0];
        #pragma unroll
        for (int i = 1; i < 3; i++) mm = fmaxf(mm, sred[i]);
        s_sc[0] = mm;
    }
    __syncthreads();
    float mloc = s_sc[0];
    float ex = (tid < cnt) ? __expf(se[tid] - mloc) : 0.f;
    if (tid < cnt) se[tid] = ex;
    float sum = ex;
    #pragma unroll
    for (int o = 16; o; o >>= 1) sum += __shfl_xor_sync(0xffffffffu, sum, o);
    if (lane == 0) sred[warp] = sum;
    __syncthreads();
    if (tid == 0){
        s_sc[1] = sred[0] + sred[1] + sred[2];
    }
    __syncthreads();

    // ---- partial ctx
    float4 a4 = {0.f, 0.f, 0.f, 0.f};
    for (int n = n0 + warp; n < n1; n += 32){
        float w = se[n - n0];
        uint2 pv = *(const uint2*)(g_Vh + ((size_t)b*Nn + n)*VD + lane*4);
        float2 lo = __half22float2(*(__half2*)&pv.x);
        float2 hi = __half22float2(*(__half2*)&pv.y);
        a4.x += w*lo.x; a4.y += w*lo.y; a4.z += w*hi.x; a4.w += w*hi.y;
    }
    sc4[warp][lane] = a4;
    __syncthreads();
    #pragma unroll
    for (int off = 16; off; off >>= 1){
        if (warp < off){
            float4 x = sc4[warp][lane], y4 = sc4[warp + off][lane];
            x.x += y4.x; x.y += y4.y; x.z += y4.z; x.w += y4.w;
            sc4[warp][lane] = x;
        }
        __syncthreads();
    }

    // ---- write partial {ctx[128], m, s}
    float* P = g_attp + (size_t)(b*NSPLA + sp)*132;
    if (tid < 32){
        float4 cv = sc4[0][tid];
        *(float4*)&P[tid*4] = cv;
    }
    if (tid == 32) P[128] = mloc;
    if (tid == 33) P[129] = s_sc[1];
    __threadfence();
    __syncthreads();
    if (tid == 0) s_old = atomicAdd(&g_acnt[b], 1);
    __syncthreads();
    if (s_old != NSPLA - 1) return;

    // ---- last arriver: combine partials + xc epilogue
    __threadfence();
    const float* P0 = g_attp + (size_t)b*NSPLA*132;
    if (tid == 0){
        float m0 = P0[128], m1 = P0[132 + 128], m2 = P0[264 + 128];
        float mg = fmaxf(m0, fmaxf(m1, m2));
        float w0 = __expf(m0 - mg), w1 = __expf(m1 - mg), w2 = __expf(m2 - mg);
        float tot = P0[129]*w0 + P0[132 + 129]*w1 + P0[264 + 129]*w2;
        s_sc[0] = w0; s_sc[1] = w1; s_sc[2] = w2; s_sc[3] = 1.0f / tot;
        g_acnt[b] = 0;
    }
    __syncthreads();
    if (tid < VD){
        float w0 = s_sc[0], w1 = s_sc[1], w2 = s_sc[2], inv = s_sc[3];
        float cv = P0[tid]*w0 + P0[132 + tid]*w1 + P0[264 + tid]*w2;
        sctx[tid] = cv * inv;
    }
    __syncthreads();

    if (tid < KG){
        int tok = y[b*Tt + step];
        float v;
        if (tid < EM)      v = embed[(size_t)tok*EM + tid];
        else if (tid < KX) v = sctx[tid - EM];
        else               v = sh[tid - KX];
        __nv_bfloat16 hb, lb; split_bf16(v, hb, lb);
        __nv_bfloat16* row = g_Axc + (size_t)b*KG2;
        row[tid]        = hb;
        row[KG + tid]   = hb;
        row[2*KG + tid] = lb;
    }
}

// ---------------- LSTM gates: K-split mma + last-arriver reduce + pointwise. grid (16,7) ----------------
#define LSTM_STG 24576
#define LSTM_SMEM 73728
#define NCHS 6

extern __shared__ char ls_smem[];

__global__ void __launch_bounds__(256, 1) lstm_mma_kernel(int step, int p){
    uint32_t sb = smem_to_u32(ls_smem);
    int tid = threadIdx.x;
    int warp = tid >> 5, lane = tid & 31;
    int wm = warp >> 2, wn = warp & 3;
    int jt = blockIdx.x, ks = blockIdx.y;
    int kbase = ks*(NCHS*64);
    const __nv_bfloat16* Bg = g_Wg2 + (size_t)jt*128*KG2;

    float acc[2][4][4];
    #pragma unroll
    for (int i = 0; i < 2; i++)
        #pragma unroll
        for (int j = 0; j < 4; j++)
            #pragma unroll
            for (int q = 0; q < 4; q++) acc[i][j][q] = 0.f;

#define LLOAD(s, kc) { \
    uint32_t base_ = sb + (uint32_t)(s)*LSTM_STG; \
    _Pragma("unroll") \
    for (int it = 0; it < 6; it++){ \
        int f = tid + it*256; \
        if (f < 512){ \
            int row = f >> 3, ch = f & 7; \
            cp_async16(base_ + (uint32_t)SWZ(row*128 + ch*16), \
                       g_Axc + (size_t)row*KG2 + (kc) + ch*8); \
        } else { \
            int fb = f - 512; \
            int row = fb >> 3, ch = fb & 7; \
            cp_async16(base_ + 8192u + (uint32_t)SWZ(row*128 + ch*16), \
                       Bg + (size_t)row*KG2 + (kc) + ch*8); \
        } \
    } \
    asm volatile("cp.async.commit_group;" ::: "memory"); \
}

    LLOAD(0, kbase);
    LLOAD(1, kbase + 64);
    LLOAD(2, kbase + 128);

    int lrow = ((lane >> 3) & 1)*8 + (lane & 7);
    int lkb  = (lane >> 4)*16;

    for (int c = 0; c < NCHS; c++){
        asm volatile("cp.async.wait_group 2;" ::: "memory");
        __syncthreads();
        int s = c % 3;
        uint32_t aBase = sb + (uint32_t)s*LSTM_STG;
        uint32_t bBase = aBase + 8192;
        #pragma unroll
        for (int k16 = 0; k16 < 4; k16++){
            int kb = k16*32 + lkb;
            uint32_t a[2][4], bfr[2][4];
            #pragma unroll
            for (int mi = 0; mi < 2; mi++){
                int row = wm*32 + mi*16 + lrow;
                ldmatrix_x4(a[mi][0], a[mi][1], a[mi][2], a[mi][3],
                            aBase + (uint32_t)SWZ(row*128 + kb));
            }
            #pragma unroll
            for (int nh = 0; nh < 2; nh++){
                int row = wn*32 + nh*16 + lrow;
                ldmatrix_x4(bfr[nh][0], bfr[nh][1], bfr[nh][2], bfr[nh][3],
                            bBase + (uint32_t)SWZ(row*128 + kb));
            }
            #pragma unroll
            for (int mi = 0; mi < 2; mi++)
                #pragma unroll
                for (int nj = 0; nj < 4; nj++)
                    mma16816(acc[mi][nj], a[mi], bfr[nj>>1][nj&1], bfr[nj>>1][(nj&1)+2]);
        }
        __syncthreads();
        if (c + 3 < NCHS){
            LLOAD((c + 3) % 3, kbase + (c + 3)*64);
        } else {
            asm volatile("cp.async.commit_group;" ::: "memory");
        }
    }
#undef LLOAD

    float* P = g_part + ((size_t)(jt*NSPL + ks))*8192;
    #pragma unroll
    for (int mi = 0; mi < 2; mi++){
        int rbase = wm*32 + mi*16 + (lane >> 2);
        #pragma unroll
        for (int half = 0; half < 2; half++){
            int r = rbase + half*8;
            #pragma unroll
            for (int nj = 0; nj < 4; nj++){
                int col = wn*32 + nj*8 + (lane & 3)*2;
                float2 v = {acc[mi][nj][half*2], acc[mi][nj][half*2 + 1]};
                *(float2*)&P[r*128 + col] = v;
            }
        }
    }
    __threadfence();
    __syncthreads();
    __shared__ int s_old;
    if (tid == 0) s_old = atomicAdd(&g_cnt[jt], 1);
    __syncthreads();
    if (s_old != NSPL - 1) return;

    __threadfence();
    float* sG = (float*)ls_smem;   // [64][132]
    const float* Pj = g_part + (size_t)jt*NSPL*8192;
    #pragma unroll
    for (int qq = 0; qq < 32; qq++){
        int idx = qq*256 + tid;
        float s = 0.f;
        #pragma unroll
        for (int k2 = 0; k2 < NSPL; k2++)
            s += Pj[k2*8192 + idx];
        sG[(idx >> 7)*132 + (idx & 127)] = s;
    }
    __syncthreads();

    int u0 = jt*32;
    int q = p ^ 1;
    #pragma unroll
    for (int qq = 0; qq < 8; qq++){
        int idx = qq*256 + tid;
        int b = idx >> 5, uu = idx & 31;
        int u = u0 + uu;
        float iv = sG[b*132 +      uu] + g_gb[u];
        float fv = sG[b*132 + 32 + uu] + g_gb[HD + u];
        float gv = sG[b*132 + 64 + uu] + g_gb[2*HD + u];
        float ov = sG[b*132 + 96 + uu] + g_gb[3*HD + u];
        float cp = g_c[p][b*HD + u];
        float cn = sigf(fv)*cp + sigf(iv)*tanhacc(gv);
        float hn = sigf(ov)*tanhacc(cn);
        g_c[q][b*HD + u] = cn;
        g_h[q][b*HD + u] = hn;
        g_H[((size_t)step*Bz + b)*HD + u] = hn;
    }
    if (tid == 0) g_cnt[jt] = 0;
}

// ---------------- proj: E = H @ proj.T, epilogue writes fp16 rows A = [hi|hi] ----------------
__global__ void __launch_bounds__(256) proj_kernel(const float* __restrict__ projw){
    __shared__ __align__(16) float sA[64][33];
    __shared__ __align__(16) float sW[64][33];
    int tid = threadIdx.x;
    int r0 = blockIdx.x*64, a0 = blockIdx.y*64;
    int tx = tid & 15, ty = tid >> 4;
    float acc[4][4] = {};
    for (int kc = 0; kc < HD; kc += 32){
        for (int e = tid; e < 64*32; e += 256){
            int row = e >> 5, col = e & 31;
            sA[row][col] = g_H[(size_t)(r0 + row)*HD + kc + col];
            sW[row][col] = projw[(size_t)(a0 + row)*HD + kc + col];
        }
        __syncthreads();
        #pragma unroll
        for (int k = 0; k < 32; k++){
            float af[4], wf[4];
            #pragma unroll
            for (int i = 0; i < 4; i++) af[i] = sA[ty*4 + i][k];
            #pragma unroll
            for (int j = 0; j < 4; j++) wf[j] = sW[tx*4 + j][k];
            #pragma unroll
            for (int i = 0; i < 4; i++)
                #pragma unroll
                for (int j = 0; j < 4; j++)
                    acc[i][j] += af[i]*wf[j];
        }
        __syncthreads();
    }
    #pragma unroll
    for (int i = 0; i < 4; i++){
        int r = r0 + ty*4 + i;
        __half* row = g_A2 + (size_t)r*K2;
        #pragma unroll
        for (int jp = 0; jp < 2; jp++){
            float x0 = acc[i][jp*2], x1 = acc[i][jp*2 + 1];
            __half h0 = __float2half_rn(x0);
            __half h1 = __float2half_rn(x1);
            uint32_t hv = (uint32_t)__half_as_ushort(h0) | ((uint32_t)__half_as_ushort(h1) << 16);
            int k = a0 + tx*4 + jp*2;
            *(uint32_t*)(row + k)       = hv;   // hi (pairs with B hi)
            *(uint32_t*)(row + 256 + k) = hv;   // hi (pairs with B lo)
        }
    }
}

// ---------------- logits: mma.sync fp16 GEMM, K=512, 128x128 tile, cp.async 3-stage ----------------
#define KCH 64
#define STG_BYTES 32768
#define LOGIT_SMEM (3*STG_BYTES)
#define LG_NCH (K2/KCH)    // 8

extern __shared__ char lg_smem[];

__global__ void __launch_bounds__(256, 2) logit_mma_kernel(float* __restrict__ out){
    uint32_t sb = smem_to_u32(lg_smem);
    int tid = threadIdx.x;
    int warp = tid >> 5, lane = tid & 31;
    int wm = warp >> 2, wn = warp & 3;
    int r0 = blockIdx.x*128, v0 = blockIdx.y*128;
    const __half* Ag = g_A2 + (size_t)r0*K2;
    const __half* Bg = g_B2 + (size_t)v0*K2;

    float acc[4][4][4];
    #pragma unroll
    for (int i = 0; i < 4; i++)
        #pragma unroll
        for (int j = 0; j < 4; j++)
            #pragma unroll
            for (int q = 0; q < 4; q++) acc[i][j][q] = 0.f;

#define LOAD_STAGE(s, kc) { \
    uint32_t base_ = sb + (uint32_t)(s)*STG_BYTES; \
    _Pragma("unroll") \
    for (int it = 0; it < 8; it++){ \
        int f = tid + it*256; \
        int side = f >> 10, idx = f & 1023; \
        int row = idx >> 3, ch = idx & 7; \
        const __half* src = (side ? Bg : Ag) + (size_t)row*K2 + (kc) + ch*8; \
        uint32_t off = (uint32_t)(side*16384 + SWZ(row*128 + ch*16)); \
        cp_async16(base_ + off, src); \
    } \
    asm volatile("cp.async.commit_group;" ::: "memory"); \
}

    LOAD_STAGE(0, 0);
    LOAD_STAGE(1, KCH);
    LOAD_STAGE(2, 2*KCH);

    int lrow = ((lane >> 3) & 1)*8 + (lane & 7);
    int lkb  = (lane >> 4)*16;

    for (int c = 0; c < LG_NCH; c++){
        asm volatile("cp.async.wait_group 2;" ::: "memory");
        __syncthreads();
        int s = c % 3;
        uint32_t aBase = sb + (uint32_t)s*STG_BYTES;
        uint32_t bBase = aBase + 16384;
        #pragma unroll
        for (int k16 = 0; k16 < 4; k16++){
            int kb = k16*32 + lkb;
            uint32_t a[4][4], bfr[2][4];
            #pragma unroll
            for (int mi = 0; mi < 4; mi++){
                int row = wm*64 + mi*16 + lrow;
                ldmatrix_x4(a[mi][0], a[mi][1], a[mi][2], a[mi][3],
                            aBase + (uint32_t)SWZ(row*128 + kb));
            }
            #pragma unroll
            for (int nh = 0; nh < 2; nh++){
                int row = wn*32 + nh*16 + lrow;
                ldmatrix_x4(bfr[nh][0], bfr[nh][1], bfr[nh][2], bfr[nh][3],
                            bBase + (uint32_t)SWZ(row*128 + kb));
            }
            #pragma unroll
            for (int mi = 0; mi < 4; mi++)
                #pragma unroll
                for (int nj = 0; nj < 4; nj++)
                    mma16816h(acc[mi][nj], a[mi], bfr[nj>>1][nj&1], bfr[nj>>1][(nj&1)+2]);
        }
        __syncthreads();
        if (c + 3 < LG_NCH){
            LOAD_STAGE((c + 3) % 3, (c + 3)*KCH);
        } else {
            asm volatile("cp.async.commit_group;" ::: "memory");
        }
    }

    #pragma unroll
    for (int mi = 0; mi < 4; mi++){
        int rbase = r0 + wm*64 + mi*16 + (lane >> 2);
        #pragma unroll
        for (int half = 0; half < 2; half++){
            int r = rbase + half*8;
            if (r < RTOT){
                int st = r >> 6, bb = r & 63;
                float* op = out + ((size_t)bb*Ss + st)*VOC;
                #pragma unroll
                for (int nj = 0; nj < 4; nj++){
                    int v = v0 + wn*32 + nj*8 + (lane & 3)*2;
                    if (v < VOC){
                        float2 val = {acc[mi][nj][half*2], acc[mi][nj][half*2 + 1]};
                        *(float2*)(op + v) = val;
                    }
                }
            }
        }
    }
#undef LOAD_STAGE
}

// ---------------- launch ----------------
extern "C" void kernel_launch(void* const* d_in, const int* in_sizes, int n_in,
                              void* d_out, int out_size){
    const float* V     = (const float*)d_in[0];
    const int*   y     = (const int*)  d_in[1];
    const float* embed = (const float*)d_in[2];
    const float* Ww    = (const float*)d_in[3];
    const float* Wb    = (const float*)d_in[4];
    const float* Uw    = (const float*)d_in[5];
    const float* Ub    = (const float*)d_in[6];
    const float* vw    = (const float*)d_in[7];
    const float* vb    = (const float*)d_in[8];
    const float* Wih   = (const float*)d_in[9];
    const float* Whh   = (const float*)d_in[10];
    const float* bih   = (const float*)d_in[11];
    const float* bhh   = (const float*)d_in[12];
    const float* projw = (const float*)d_in[13];
    float* out = (float*)d_out;

    cudaFuncSetAttribute(logit_mma_kernel,
                         cudaFuncAttributeMaxDynamicSharedMemorySize, LOGIT_SMEM);
    cudaFuncSetAttribute(lstm_mma_kernel,
                         cudaFuncAttributeMaxDynamicSharedMemorySize, LSTM_SMEM);

    // launch #4 = attn_kernel (ncu profiles #4)
    uv_kernel<<<dim3(Bz, 7), 256>>>(V, Uw, Ub);                                   // 1
    prep_w_kernel<<<2184, 256>>>(Wih, Whh, Ww, bih, bhh);                         // 2
    conv_embed_kernel<<<(VOC*EM)/(256*4), 256>>>(embed);                          // 3
    attn_kernel<<<dim3(Bz, NSPLA), 1024>>>(y, embed, Wb, vw, vb, 0, 0);           // 4 <- profiled
    lstm_mma_kernel<<<dim3(16, NSPL), 256, LSTM_SMEM>>>(0, 0);                    // 5

    for (int j = 1; j < Ss; j++){
        int p = j & 1;
        attn_kernel<<<dim3(Bz, NSPLA), 1024>>>(y, embed, Wb, vw, vb, j, p);
        lstm_mma_kernel<<<dim3(16, NSPL), 256, LSTM_SMEM>>>(j, p);
    }

    proj_kernel<<<dim3(Ss, 4), 256>>>(projw);
    logit_mma_kernel<<<dim3(RP/128, VOCP/128), 256, LOGIT_SMEM>>>(out);
}

// round 17
// speedup vs baseline: 1.2895x; 1.0695x over previous
#include <cuda_runtime.h>
#include <cuda_bf16.h>
#include <cuda_fp16.h>
#include <math.h>
#include <cstdint>

#define Bz 64
#define Nn 196
#define Tt 32
#define Ss 31
#define VD 128
#define EM 256
#define AT 256
#define HD 512
#define VOC 30000
#define VOCP 30080
#define KX 384      // EM + VD
#define KG 896      // EM + VD + HD
#define JG 2048     // 4*HD
#define RTOT 1984   // Ss*Bz
#define RP 2048
#define K2 512      // logit fp16 2-term split K: A=[hi|hi], B=[hi|lo]
#define KG2 2688    // lstm split-concat K = 3*896
#define NSPL 7      // lstm K-splits
#define NSPLA 4     // attn n-splits (49 each; 4*49 = 196)

typedef unsigned long long ULL;

// ---------------- scratch (device globals; zero-initialized, no allocation) ----------------
__device__ float g_h[2][Bz*HD];
__device__ float g_c[2][Bz*HD];
__device__ float g_H[Ss*Bz*HD];
__device__ float g_WwT[HD*AT];                 // Ww transposed [k][a]
__device__ float g_gb[JG];                     // bih + bhh
__device__ float g_part[16*NSPL*64*128];       // lstm partial gates
__device__ int   g_cnt[16];                    // lstm arrival counters (reset in-kernel)
__device__ float g_attp[Bz*NSPLA*132];         // attn partials: {ctx[128], m, s}
__device__ int   g_acnt[Bz];                   // attn ctx arrival counters (reset in-kernel)
__device__ float g_whp[Bz*NSPLA*AT];           // Wh k-slice partials
__device__ int   g_wcnt[Bz];                   // Wh spin counters (monotonic per replay; reset in prep)
__device__ __half g_UVh[Bz*Nn*AT];             // UV in fp16 (6.4MB)
__device__ __half g_Vh[Bz*Nn*VD];              // V copy in fp16 (3.2MB)
__device__ __nv_bfloat16 g_Axc[Bz*KG2];        // per-step xc rows [hi|hi|lo]
__device__ __nv_bfloat16 g_Wg2[JG*KG2];        // gate-interleaved weight rows [hi|lo|hi]
__device__ __half g_A2[RP*K2];                 // E fp16 rows [hi|hi]; pad rows stay 0
__device__ __half g_B2[VOCP*K2];               // embed fp16 rows [hi|lo]; pad rows stay 0

// ---------------- helpers ----------------
__device__ __forceinline__ float sigf(float x){ return __fdividef(1.0f, 1.0f + __expf(-x)); }
__device__ __forceinline__ float tanhacc(float x){
    return __fdividef(2.0f, 1.0f + __expf(-2.0f*x)) - 1.0f;
}
__device__ __forceinline__ __half2 htanh2(__half2 x){
    uint32_t r, xi = *(uint32_t*)&x;
    asm("tanh.approx.f16x2 %0, %1;" : "=r"(r) : "r"(xi));
    return *(__half2*)&r;
}
__device__ __forceinline__ uint32_t smem_to_u32(const void* smem_ptr){
    uint32_t addr;
    asm("{ .reg .u64 tmp; cvta.to.shared.u64 tmp, %1; cvt.u32.u64 %0, tmp; }"
        : "=r"(addr) : "l"(smem_ptr));
    return addr;
}
#define SWZ(o) ((o) ^ (((o) >> 3) & 0x70))

__device__ __forceinline__ void ldmatrix_x4(uint32_t& r0, uint32_t& r1, uint32_t& r2, uint32_t& r3,
                                            uint32_t addr){
    asm volatile("ldmatrix.sync.aligned.m8n8.x4.shared.b16 {%0,%1,%2,%3}, [%4];"
                 : "=r"(r0), "=r"(r1), "=r"(r2), "=r"(r3) : "r"(addr));
}
__device__ __forceinline__ void mma16816(float* d, const uint32_t* a, uint32_t b0, uint32_t b1){
    asm volatile("mma.sync.aligned.m16n8k16.row.col.f32.bf16.bf16.f32 "
                 "{%0,%1,%2,%3}, {%4,%5,%6,%7}, {%8,%9}, {%0,%1,%2,%3};"
                 : "+f"(d[0]), "+f"(d[1]), "+f"(d[2]), "+f"(d[3])
                 : "r"(a[0]), "r"(a[1]), "r"(a[2]), "r"(a[3]), "r"(b0), "r"(b1));
}
__device__ __forceinline__ void mma16816h(float* d, const uint32_t* a, uint32_t b0, uint32_t b1){
    asm volatile("mma.sync.aligned.m16n8k16.row.col.f32.f16.f16.f32 "
                 "{%0,%1,%2,%3}, {%4,%5,%6,%7}, {%8,%9}, {%0,%1,%2,%3};"
                 : "+f"(d[0]), "+f"(d[1]), "+f"(d[2]), "+f"(d[3])
                 : "r"(a[0]), "r"(a[1]), "r"(a[2]), "r"(a[3]), "r"(b0), "r"(b1));
}
__device__ __forceinline__ void cp_async16(uint32_t dst, const void* src){
    asm volatile("cp.async.cg.shared.global [%0], [%1], 16;" :: "r"(dst), "l"(src) : "memory");
}
__device__ __forceinline__ void split_bf16(float x, __nv_bfloat16& h, __nv_bfloat16& l){
    h = __float2bfloat16(x);
    l = __float2bfloat16(x - __bfloat162float(h));
}
__device__ __forceinline__ void split_f16(float x, __half& h, __half& l){
    h = __float2half_rn(x);
    l = __float2half_rn(x - __half2float(h));
}

// ---------------- embed -> fp16 split rows: B = [hi|lo] ----------------
__global__ void __launch_bounds__(256) conv_embed_kernel(const float* __restrict__ embed){
    size_t i = ((size_t)blockIdx.x*256 + threadIdx.x)*4;
    size_t v = i / EM;
    int k = (int)(i % EM);
    float4 x = *(const float4*)(embed + i);
    float xs[4] = {x.x, x.y, x.z, x.w};
    unsigned short h[4], l[4];
    #pragma unroll
    for (int j = 0; j < 4; j++){
        __half hb, lb; split_f16(xs[j], hb, lb);
        h[j] = __half_as_ushort(hb);
        l[j] = __half_as_ushort(lb);
    }
    uint2 hv, lv;
    hv.x = (uint32_t)h[0] | ((uint32_t)h[1] << 16);
    hv.y = (uint32_t)h[2] | ((uint32_t)h[3] << 16);
    lv.x = (uint32_t)l[0] | ((uint32_t)l[1] << 16);
    lv.y = (uint32_t)l[2] | ((uint32_t)l[3] << 16);
    __half* row = g_B2 + v*K2;
    *(uint2*)(row + k)       = hv;
    *(uint2*)(row + 256 + k) = lv;
}

// ---------------- one-shot prep: Wg2 rows + misc + WwT transpose ----------------
__global__ void __launch_bounds__(256) prep_w_kernel(const float* __restrict__ Wih,
                                                     const float* __restrict__ Whh,
                                                     const float* __restrict__ Ww,
                                                     const float* __restrict__ bih,
                                                     const float* __restrict__ bhh){
    int bx = blockIdx.x, tid = threadIdx.x;
    if (bx < JG){
        int tile = bx >> 7;
        int within = bx & 127;
        int gate = within >> 5;
        int uu = within & 31;
        int j = gate*HD + tile*32 + uu;
        __nv_bfloat16* row = g_Wg2 + (size_t)bx*KG2;
        for (int k = tid; k < KG; k += 256){
            float w = (k < KX) ? Wih[(size_t)j*KX + k] : Whh[(size_t)j*HD + (k - KX)];
            __nv_bfloat16 hb, lb; split_bf16(w, hb, lb);
            row[k]        = hb;
            row[KG + k]   = lb;
            row[2*KG + k] = hb;
        }
    } else if (bx < JG + 8){
        int bb = bx - JG;
        int idx = bb*256 + tid;           // 0..2047
        g_gb[idx] = bih[idx] + bhh[idx];
        if (idx < Bz) g_wcnt[idx] = 0;    // reset Wh spin counters each replay
        #pragma unroll
        for (int i = 0; i < 16; i++){
            int z = idx*16 + i;
            g_h[0][z] = 0.f;
            g_c[0][z] = 0.f;
        }
    } else {
        __shared__ float t[32][33];
        int bx2 = bx - (JG + 8);
        int a0 = (bx2 & 7)*32;
        int k0 = (bx2 >> 3)*32;
        int tx = tid & 31, ty = tid >> 5;
        #pragma unroll
        for (int i = 0; i < 4; i++)
            t[ty + i*8][tx] = Ww[(size_t)(a0 + ty + i*8)*HD + k0 + tx];
        __syncthreads();
        #pragma unroll
        for (int i = 0; i < 4; i++)
            g_WwT[(size_t)(k0 + ty + i*8)*AT + a0 + tx] = t[tx][ty + i*8];
    }
}

// ---------------- UV (writes fp16 UV + fp16 V copy) ----------------
__global__ void __launch_bounds__(256) uv_kernel(const float* __restrict__ V,
                                                 const float* __restrict__ Uw,
                                                 const float* __restrict__ Ub){
    int b = blockIdx.x;
    int n0 = blockIdx.y * 32;
    int tid = threadIdx.x;
    __shared__ __align__(16) float sV[32][VD];
    for (int e = tid; e < 32*VD; e += 256){
        int n = n0 + (e / VD);
        float v = (n < Nn) ? V[((size_t)b*Nn + n)*VD + (e % VD)] : 0.f;
        sV[e / VD][e % VD] = v;
        if (n < Nn) g_Vh[((size_t)b*Nn + n)*VD + (e % VD)] = __float2half_rn(v);
    }
    __syncthreads();
    int a = tid;
    float acc[32];
    #pragma unroll
    for (int n = 0; n < 32; n++) acc[n] = 0.f;
    for (int kc = 0; kc < VD; kc += 16){
        float u[16];
        #pragma unroll
        for (int i = 0; i < 16; i += 4)
            *(float4*)&u[i] = *(const float4*)&Uw[a*VD + kc + i];
        #pragma unroll
        for (int n = 0; n < 32; n++){
            #pragma unroll
            for (int k = 0; k < 16; k++)
                acc[n] += u[k] * sV[n][kc + k];
        }
    }
    float ub = Ub[a];
    #pragma unroll
    for (int n = 0; n < 32; n++){
        int nn = n0 + n;
        if (nn < Nn) g_UVh[((size_t)b*Nn + nn)*AT + a] = __float2half_rn(acc[n] + ub);
    }
}

// ---------------- fused Wh + attention (flash n-split x4). grid (64,4), 1024 thr, 2 CTA/SM ----------------
__global__ void __launch_bounds__(1024, 2) attn_kernel(const int* __restrict__ y,
                                                       const float* __restrict__ embed,
                                                       const float* __restrict__ Wb,
                                                       const float* __restrict__ vw,
                                                       const float* __restrict__ vb,
                                                       int step, int p){
    __shared__ __align__(16) float sh[HD];
    __shared__ __align__(16) float sP[1024];
    __shared__ __align__(16) __half2 sWh2[AT/2];
    __shared__ __align__(16) float sv[AT];
    __shared__ __align__(16) float se[52];
    __shared__ __align__(16) float sred[32];
    __shared__ __align__(16) float s_sc[NSPLA + 1];
    __shared__ __align__(16) float sctx[VD];
    __shared__ __align__(16) float4 sc4[32][32];
    __shared__ int s_old;

    int b = blockIdx.x, sp = blockIdx.y, tid = threadIdx.x;
    int warp = tid >> 5, lane = tid & 31;
    int n0 = sp*49;
    int n1 = n0 + 49;
    int cnt = 49;

    if (tid < HD) sh[tid] = g_h[p][b*HD + tid];
    if (tid < AT) sv[tid] = vw[tid];
    __syncthreads();

    // ---- phase 0: Wh k-slice partial. k-range [sp*128, sp*128+128), all 256 a
    {
        int k0 = sp*128;
        int k1 = k0 + 128;
        int a = tid & 255, kq = tid >> 8;
        float acc = 0.f;
        for (int k = k0 + kq; k < k1; k += 4)
            acc += sh[k] * g_WwT[(size_t)k*AT + a];
        sP[tid] = acc;
    }
    __syncthreads();
    if (tid < AT)
        g_whp[(size_t)(b*NSPLA + sp)*AT + tid] =
            sP[tid] + sP[256 + tid] + sP[512 + tid] + sP[768 + tid];
    __threadfence();
    __syncthreads();
    if (tid == 0){
        atomicAdd(&g_wcnt[b], 1);
        int target = NSPLA*(step + 1);
        while (atomicAdd(&g_wcnt[b], 0) < target){ __nanosleep(64); }
    }
    __syncthreads();
    __threadfence();
    if (tid < AT/2){
        const float* W0 = g_whp + (size_t)b*NSPLA*AT;
        int a0 = 2*tid, a1 = 2*tid + 1;
        float x0 = Wb[a0], x1 = Wb[a1];
        #pragma unroll
        for (int i = 0; i < NSPLA; i++){
            x0 += W0[i*AT + a0];
            x1 += W0[i*AT + a1];
        }
        sWh2[tid] = __floats2half2_rn(x0, x1);
    }
    __syncthreads();

    // ---- local e_n = v . tanh(Wh + UV[n]) + vb
    float vbias = vb[0];
    for (int n = n0 + warp; n < n1; n += 32){
        const uint32_t* uvp = (const uint32_t*)(g_UVh + ((size_t)b*Nn + n)*AT);
        float pz = 0.f;
        #pragma unroll
        for (int j = 0; j < 4; j++){
            int idx = lane + j*32;
            uint32_t pa = uvp[idx];
            __half2 s2 = __hadd2(sWh2[idx], *(__half2*)&pa);
            float2 t = __half22float2(htanh2(s2));
            float2 v2 = *(const float2*)&sv[2*idx];
            pz += t.x*v2.x + t.y*v2.y;
        }
        #pragma unroll
        for (int o = 16; o; o >>= 1) pz += __shfl_xor_sync(0xffffffffu, pz, o);
        if (lane == 0) se[n - n0] = pz + vbias;
    }
    __syncthreads();

    // ---- local max + exp + sum (cnt=49 spans warps 0..1)
    float m = (tid < cnt) ? se[tid] : -1e30f;
    #pragma unroll
    for (int o = 16; o; o >>= 1) m = fmaxf(m, __shfl_xor_sync(0xffffffffu, m, o));
    if (lane == 0) sred[warp] = m;
    __syncthreads();
    if (tid == 0){
        s_sc[0] = fmaxf(sred[0], sred[1]);
    }
    __syncthreads();
    float mloc = s_sc[0];
    float ex = (tid < cnt) ? __expf(se[tid] - mloc) : 0.f;
    if (tid < cnt) se[tid] = ex;
    float sum = ex;
    #pragma unroll
    for (int o = 16; o; o >>= 1) sum += __shfl_xor_sync(0xffffffffu, sum, o);
    if (lane == 0) sred[warp] = sum;
    __syncthreads();
    if (tid == 0){
        s_sc[1] = sred[0] + sred[1];
    }
    __syncthreads();

    // ---- partial ctx
    float4 a4 = {0.f, 0.f, 0.f, 0.f};
    for (int n = n0 + warp; n < n1; n += 32){
        float w = se[n - n0];
        uint2 pv = *(const uint2*)(g_Vh + ((size_t)b*Nn + n)*VD + lane*4);
        float2 lo = __half22float2(*(__half2*)&pv.x);
        float2 hi = __half22float2(*(__half2*)&pv.y);
        a4.x += w*lo.x; a4.y += w*lo.y; a4.z += w*hi.x; a4.w += w*hi.y;
    }
    sc4[warp][lane] = a4;
    __syncthreads();
    #pragma unroll
    for (int off = 16; off; off >>= 1){
        if (warp < off){
            float4 x = sc4[warp][lane], y4 = sc4[warp + off][lane];
            x.x += y4.x; x.y += y4.y; x.z += y4.z; x.w += y4.w;
            sc4[warp][lane] = x;
        }
        __syncthreads();
    }

    // ---- write partial {ctx[128], m, s}
    float* P = g_attp + (size_t)(b*NSPLA + sp)*132;
    if (tid < 32){
        float4 cv = sc4[0][tid];
        *(float4*)&P[tid*4] = cv;
    }
    if (tid == 32) P[128] = s_sc[0];
    if (tid == 33) P[129] = s_sc[1];
    __threadfence();
    __syncthreads();
    if (tid == 0) s_old = atomicAdd(&g_acnt[b], 1);
    __syncthreads();
    if (s_old != NSPLA - 1) return;

    // ---- last arriver: combine partials + xc epilogue
    __threadfence();
    const float* P0 = g_attp + (size_t)b*NSPLA*132;
    if (tid == 0){
        float mg = -1e30f;
        #pragma unroll
        for (int i = 0; i < NSPLA; i++) mg = fmaxf(mg, P0[i*132 + 128]);
        float tot = 0.f;
        #pragma unroll
        for (int i = 0; i < NSPLA; i++){
            float w = __expf(P0[i*132 + 128] - mg);
            s_sc[i] = w;
            tot += P0[i*132 + 129]*w;
        }
        s_sc[NSPLA] = 1.0f / tot;
        g_acnt[b] = 0;
    }
    __syncthreads();
    if (tid < VD){
        float cv = 0.f;
        #pragma unroll
        for (int i = 0; i < NSPLA; i++)
            cv += P0[i*132 + tid]*s_sc[i];
        sctx[tid] = cv * s_sc[NSPLA];
    }
    __syncthreads();

    if (tid < KG){
        int tok = y[b*Tt + step];
        float v;
        if (tid < EM)      v = embed[(size_t)tok*EM + tid];
        else if (tid < KX) v = sctx[tid - EM];
        else               v = sh[tid - KX];
        __nv_bfloat16 hb, lb; split_bf16(v, hb, lb);
        __nv_bfloat16* row = g_Axc + (size_t)b*KG2;
        row[tid]        = hb;
        row[KG + tid]   = hb;
        row[2*KG + tid] = lb;
    }
}

// ---------------- LSTM gates: K-split mma + last-arriver reduce + pointwise. grid (16,7) ----------------
#define LSTM_STG 24576
#define LSTM_SMEM 73728
#define NCHS 6

extern __shared__ char ls_smem[];

__global__ void __launch_bounds__(256, 1) lstm_mma_kernel(int step, int p){
    uint32_t sb = smem_to_u32(ls_smem);
    int tid = threadIdx.x;
    int warp = tid >> 5, lane = tid & 31;
    int wm = warp >> 2, wn = warp & 3;
    int jt = blockIdx.x, ks = blockIdx.y;
    int kbase = ks*(NCHS*64);
    const __nv_bfloat16* Bg = g_Wg2 + (size_t)jt*128*KG2;

    float acc[2][4][4];
    #pragma unroll
    for (int i = 0; i < 2; i++)
        #pragma unroll
        for (int j = 0; j < 4; j++)
            #pragma unroll
            for (int q = 0; q < 4; q++) acc[i][j][q] = 0.f;

#define LLOAD(s, kc) { \
    uint32_t base_ = sb + (uint32_t)(s)*LSTM_STG; \
    _Pragma("unroll") \
    for (int it = 0; it < 6; it++){ \
        int f = tid + it*256; \
        if (f < 512){ \
            int row = f >> 3, ch = f & 7; \
            cp_async16(base_ + (uint32_t)SWZ(row*128 + ch*16), \
                       g_Axc + (size_t)row*KG2 + (kc) + ch*8); \
        } else { \
            int fb = f - 512; \
            int row = fb >> 3, ch = fb & 7; \
            cp_async16(base_ + 8192u + (uint32_t)SWZ(row*128 + ch*16), \
                       Bg + (size_t)row*KG2 + (kc) + ch*8); \
        } \
    } \
    asm volatile("cp.async.commit_group;" ::: "memory"); \
}

    LLOAD(0, kbase);
    LLOAD(1, kbase + 64);
    LLOAD(2, kbase + 128);

    int lrow = ((lane >> 3) & 1)*8 + (lane & 7);
    int lkb  = (lane >> 4)*16;

    for (int c = 0; c < NCHS; c++){
        asm volatile("cp.async.wait_group 2;" ::: "memory");
        __syncthreads();
        int s = c % 3;
        uint32_t aBase = sb + (uint32_t)s*LSTM_STG;
        uint32_t bBase = aBase + 8192;
        #pragma unroll
        for (int k16 = 0; k16 < 4; k16++){
            int kb = k16*32 + lkb;
            uint32_t a[2][4], bfr[2][4];
            #pragma unroll
            for (int mi = 0; mi < 2; mi++){
                int row = wm*32 + mi*16 + lrow;
                ldmatrix_x4(a[mi][0], a[mi][1], a[mi][2], a[mi][3],
                            aBase + (uint32_t)SWZ(row*128 + kb));
            }
            #pragma unroll
            for (int nh = 0; nh < 2; nh++){
                int row = wn*32 + nh*16 + lrow;
                ldmatrix_x4(bfr[nh][0], bfr[nh][1], bfr[nh][2], bfr[nh][3],
                            bBase + (uint32_t)SWZ(row*128 + kb));
            }
            #pragma unroll
            for (int mi = 0; mi < 2; mi++)
                #pragma unroll
                for (int nj = 0; nj < 4; nj++)
                    mma16816(acc[mi][nj], a[mi], bfr[nj>>1][nj&1], bfr[nj>>1][(nj&1)+2]);
        }
        __syncthreads();
        if (c + 3 < NCHS){
            LLOAD((c + 3) % 3, kbase + (c + 3)*64);
        } else {
            asm volatile("cp.async.commit_group;" ::: "memory");
        }
    }
#undef LLOAD

    float* P = g_part + ((size_t)(jt*NSPL + ks))*8192;
    #pragma unroll
    for (int mi = 0; mi < 2; mi++){
        int rbase = wm*32 + mi*16 + (lane >> 2);
        #pragma unroll
        for (int half = 0; half < 2; half++){
            int r = rbase + half*8;
            #pragma unroll
            for (int nj = 0; nj < 4; nj++){
                int col = wn*32 + nj*8 + (lane & 3)*2;
                float2 v = {acc[mi][nj][half*2], acc[mi][nj][half*2 + 1]};
                *(float2*)&P[r*128 + col] = v;
            }
        }
    }
    __threadfence();
    __syncthreads();
    __shared__ int s_old;
    if (tid == 0) s_old = atomicAdd(&g_cnt[jt], 1);
    __syncthreads();
    if (s_old != NSPL - 1) return;

    __threadfence();
    float* sG = (float*)ls_smem;   // [64][132]
    const float* Pj = g_part + (size_t)jt*NSPL*8192;
    #pragma unroll
    for (int qq = 0; qq < 32; qq++){
        int idx = qq*256 + tid;
        float s = 0.f;
        #pragma unroll
        for (int k2 = 0; k2 < NSPL; k2++)
            s += Pj[k2*8192 + idx];
        sG[(idx >> 7)*132 + (idx & 127)] = s;
    }
    __syncthreads();

    int u0 = jt*32;
    int q = p ^ 1;
    #pragma unroll
    for (int qq = 0; qq < 8; qq++){
        int idx = qq*256 + tid;
        int b = idx >> 5, uu = idx & 31;
        int u = u0 + uu;
        float iv = sG[b*132 +      uu] + g_gb[u];
        float fv = sG[b*132 + 32 + uu] + g_gb[HD + u];
        float gv = sG[b*132 + 64 + uu] + g_gb[2*HD + u];
        float ov = sG[b*132 + 96 + uu] + g_gb[3*HD + u];
        float cp = g_c[p][b*HD + u];
        float cn = sigf(fv)*cp + sigf(iv)*tanhacc(gv);
        float hn = sigf(ov)*tanhacc(cn);
        g_c[q][b*HD + u] = cn;
        g_h[q][b*HD + u] = hn;
        g_H[((size_t)step*Bz + b)*HD + u] = hn;
    }
    if (tid == 0) g_cnt[jt] = 0;
}

// ---------------- proj: E = H @ proj.T, epilogue writes fp16 rows A = [hi|hi] ----------------
__global__ void __launch_bounds__(256) proj_kernel(const float* __restrict__ projw){
    __shared__ __align__(16) float sA[64][33];
    __shared__ __align__(16) float sW[64][33];
    int tid = threadIdx.x;
    int r0 = blockIdx.x*64, a0 = blockIdx.y*64;
    int tx = tid & 15, ty = tid >> 4;
    float acc[4][4] = {};
    for (int kc = 0; kc < HD; kc += 32){
        for (int e = tid; e < 64*32; e += 256){
            int row = e >> 5, col = e & 31;
            sA[row][col] = g_H[(size_t)(r0 + row)*HD + kc + col];
            sW[row][col] = projw[(size_t)(a0 + row)*HD + kc + col];
        }
        __syncthreads();
        #pragma unroll
        for (int k = 0; k < 32; k++){
            float af[4], wf[4];
            #pragma unroll
            for (int i = 0; i < 4; i++) af[i] = sA[ty*4 + i][k];
            #pragma unroll
            for (int j = 0; j < 4; j++) wf[j] = sW[tx*4 + j][k];
            #pragma unroll
            for (int i = 0; i < 4; i++)
                #pragma unroll
                for (int j = 0; j < 4; j++)
                    acc[i][j] += af[i]*wf[j];
        }
        __syncthreads();
    }
    #pragma unroll
    for (int i = 0; i < 4; i++){
        int r = r0 + ty*4 + i;
        __half* row = g_A2 + (size_t)r*K2;
        #pragma unroll
        for (int jp = 0; jp < 2; jp++){
            float x0 = acc[i][jp*2], x1 = acc[i][jp*2 + 1];
            __half h0 = __float2half_rn(x0);
            __half h1 = __float2half_rn(x1);
            uint32_t hv = (uint32_t)__half_as_ushort(h0) | ((uint32_t)__half_as_ushort(h1) << 16);
            int k = a0 + tx*4 + jp*2;
            *(uint32_t*)(row + k)       = hv;
            *(uint32_t*)(row + 256 + k) = hv;
        }
    }
}

// ---------------- logits: mma.sync fp16 GEMM, K=512, 128x128 tile, cp.async 3-stage ----------------
#define KCH 64
#define STG_BYTES 32768
#define LOGIT_SMEM (3*STG_BYTES)
#define LG_NCH (K2/KCH)    // 8

extern __shared__ char lg_smem[];

__global__ void __launch_bounds__(256, 2) logit_mma_kernel(float* __restrict__ out){
    uint32_t sb = smem_to_u32(lg_smem);
    int tid = threadIdx.x;
    int warp = tid >> 5, lane = tid & 31;
    int wm = warp >> 2, wn = warp & 3;
    int r0 = blockIdx.x*128, v0 = blockIdx.y*128;
    const __half* Ag = g_A2 + (size_t)r0*K2;
    const __half* Bg = g_B2 + (size_t)v0*K2;

    float acc[4][4][4];
    #pragma unroll
    for (int i = 0; i < 4; i++)
        #pragma unroll
        for (int j = 0; j < 4; j++)
            #pragma unroll
            for (int q = 0; q < 4; q++) acc[i][j][q] = 0.f;

#define LOAD_STAGE(s, kc) { \
    uint32_t base_ = sb + (uint32_t)(s)*STG_BYTES; \
    _Pragma("unroll") \
    for (int it = 0; it < 8; it++){ \
        int f = tid + it*256; \
        int side = f >> 10, idx = f & 1023; \
        int row = idx >> 3, ch = idx & 7; \
        const __half* src = (side ? Bg : Ag) + (size_t)row*K2 + (kc) + ch*8; \
        uint32_t off = (uint32_t)(side*16384 + SWZ(row*128 + ch*16)); \
        cp_async16(base_ + off, src); \
    } \
    asm volatile("cp.async.commit_group;" ::: "memory"); \
}

    LOAD_STAGE(0, 0);
    LOAD_STAGE(1, KCH);
    LOAD_STAGE(2, 2*KCH);

    int lrow = ((lane >> 3) & 1)*8 + (lane & 7);
    int lkb  = (lane >> 4)*16;

    for (int c = 0; c < LG_NCH; c++){
        asm volatile("cp.async.wait_group 2;" ::: "memory");
        __syncthreads();
        int s = c % 3;
        uint32_t aBase = sb + (uint32_t)s*STG_BYTES;
        uint32_t bBase = aBase + 16384;
        #pragma unroll
        for (int k16 = 0; k16 < 4; k16++){
            int kb = k16*32 + lkb;
            uint32_t a[4][4], bfr[2][4];
            #pragma unroll
            for (int mi = 0; mi < 4; mi++){
                int row = wm*64 + mi*16 + lrow;
                ldmatrix_x4(a[mi][0], a[mi][1], a[mi][2], a[mi][3],
                            aBase + (uint32_t)SWZ(row*128 + kb));
            }
            #pragma unroll
            for (int nh = 0; nh < 2; nh++){
                int row = wn*32 + nh*16 + lrow;
                ldmatrix_x4(bfr[nh][0], bfr[nh][1], bfr[nh][2], bfr[nh][3],
                            bBase + (uint32_t)SWZ(row*128 + kb));
            }
            #pragma unroll
            for (int mi = 0; mi < 4; mi++)
                #pragma unroll
                for (int nj = 0; nj < 4; nj++)
                    mma16816h(acc[mi][nj], a[mi], bfr[nj>>1][nj&1], bfr[nj>>1][(nj&1)+2]);
        }
        __syncthreads();
        if (c + 3 < LG_NCH){
            LOAD_STAGE((c + 3) % 3, (c + 3)*KCH);
        } else {
            asm volatile("cp.async.commit_group;" ::: "memory");
        }
    }

    #pragma unroll
    for (int mi = 0; mi < 4; mi++){
        int rbase = r0 + wm*64 + mi*16 + (lane >> 2);
        #pragma unroll
        for (int half = 0; half < 2; half++){
            int r = rbase + half*8;
            if (r < RTOT){
                int st = r >> 6, bb = r & 63;
                float* op = out + ((size_t)bb*Ss + st)*VOC;
                #pragma unroll
                for (int nj = 0; nj < 4; nj++){
                    int v = v0 + wn*32 + nj*8 + (lane & 3)*2;
                    if (v < VOC){
                        float2 val = {acc[mi][nj][half*2], acc[mi][nj][half*2 + 1]};
                        *(float2*)(op + v) = val;
                    }
                }
            }
        }
    }
#undef LOAD_STAGE
}

// ---------------- launch ----------------
extern "C" void kernel_launch(void* const* d_in, const int* in_sizes, int n_in,
                              void* d_out, int out_size){
    const float* V     = (const float*)d_in[0];
    const int*   y     = (const int*)  d_in[1];
    const float* embed = (const float*)d_in[2];
    const float* Ww    = (const float*)d_in[3];
    const float* Wb    = (const float*)d_in[4];
    const float* Uw    = (const float*)d_in[5];
    const float* Ub    = (const float*)d_in[6];
    const float* vw    = (const float*)d_in[7];
    const float* vb    = (const float*)d_in[8];
    const float* Wih   = (const float*)d_in[9];
    const float* Whh   = (const float*)d_in[10];
    const float* bih   = (const float*)d_in[11];
    const float* bhh   = (const float*)d_in[12];
    const float* projw = (const float*)d_in[13];
    float* out = (float*)d_out;

    cudaFuncSetAttribute(logit_mma_kernel,
                         cudaFuncAttributeMaxDynamicSharedMemorySize, LOGIT_SMEM);
    cudaFuncSetAttribute(lstm_mma_kernel,
                         cudaFuncAttributeMaxDynamicSharedMemorySize, LSTM_SMEM);

    // launch #4 = attn_kernel (ncu profiles #4)
    uv_kernel<<<dim3(Bz, 7), 256>>>(V, Uw, Ub);                                   // 1
    prep_w_kernel<<<2184, 256>>>(Wih, Whh, Ww, bih, bhh);                         // 2
    conv_embed_kernel<<<(VOC*EM)/(256*4), 256>>>(embed);                          // 3
    attn_kernel<<<dim3(Bz, NSPLA), 1024>>>(y, embed, Wb, vw, vb, 0, 0);           // 4 <- profiled
    lstm_mma_kernel<<<dim3(16, NSPL), 256, LSTM_SMEM>>>(0, 0);                    // 5

    for (int j = 1; j < Ss; j++){
        int p = j & 1;
        attn_kernel<<<dim3(Bz, NSPLA), 1024>>>(y, embed, Wb, vw, vb, j, p);
        lstm_mma_kernel<<<dim3(16, NSPL), 256, LSTM_SMEM>>>(j, p);
    }

    proj_kernel<<<dim3(Ss, 4), 256>>>(projw);
    logit_mma_kernel<<<dim3(RP/128, VOCP/128), 256, LOGIT_SMEM>>>(out);
}